// round 6
// baseline (speedup 1.0000x reference)
#include <cuda_runtime.h>
#include <cuda_fp16.h>
#include <cstdint>

#define BB 8
#define NN 1024
#define CC 256
#define HH 8
#define HD 32
#define TABLE 10

// Scratch (allocation-free rule: __device__ globals)
__device__ __half g_ah [BB*NN*CC];      // X in fp16, row-major [8192][256]
__device__ __half g_wqt[3*CC*CC];       // W_qkv^T fp16 [768][256]
__device__ __half g_wpt[CC*CC];         // W_proj^T fp16 [256][256]
__device__ __half g_qh [BB*HH*NN*HD];   // pre-scaled q, fp16
__device__ __half g_kh [BB*HH*NN*HD];
__device__ __half g_vh [BB*HH*NN*HD];
__device__ __half g_xh [BB*NN*CC];      // attention output fp16 [8192][256]

// ---------------------------------------------------------------------------
// helpers
// ---------------------------------------------------------------------------
__device__ __forceinline__ void mma_f16(float* c, const uint32_t* a, const uint32_t* b) {
    asm volatile(
        "mma.sync.aligned.m16n8k16.row.col.f32.f16.f16.f32 "
        "{%0,%1,%2,%3},{%4,%5,%6,%7},{%8,%9},{%0,%1,%2,%3};\n"
        : "+f"(c[0]), "+f"(c[1]), "+f"(c[2]), "+f"(c[3])
        : "r"(a[0]), "r"(a[1]), "r"(a[2]), "r"(a[3]), "r"(b[0]), "r"(b[1]));
}
__device__ __forceinline__ void ldsm4(uint32_t* r, uint32_t addr) {
    asm volatile("ldmatrix.sync.aligned.m8n8.x4.shared.b16 {%0,%1,%2,%3},[%4];"
                 : "=r"(r[0]), "=r"(r[1]), "=r"(r[2]), "=r"(r[3]) : "r"(addr));
}
__device__ __forceinline__ uint32_t smem_u32(const void* p) {
    uint32_t a;
    asm("{ .reg .u64 t; cvta.to.shared.u64 t, %1; cvt.u32.u64 %0, t; }" : "=r"(a) : "l"(p));
    return a;
}
__device__ __forceinline__ void cp16(uint32_t dst, const void* src) {
    asm volatile("cp.async.ca.shared.global [%0],[%1],16;" :: "r"(dst), "l"(src));
}
__device__ __forceinline__ void cp_commit() { asm volatile("cp.async.commit_group;"); }
__device__ __forceinline__ void cp_wait0()  { asm volatile("cp.async.wait_group 0;"); }
__device__ __forceinline__ uint32_t h2pack(float lo, float hi) {
    __half2 h = __floats2half2_rn(lo, hi);
    return *(uint32_t*)&h;
}
__device__ __forceinline__ uint32_t prmt(uint32_t a, uint32_t b, uint32_t s) {
    uint32_t d;
    asm("prmt.b32 %0,%1,%2,%3;" : "=r"(d) : "r"(a), "r"(b), "r"(s));
    return d;
}

// ---------------------------------------------------------------------------
// Conversions
// ---------------------------------------------------------------------------
__global__ void __launch_bounds__(256) convert_x_kernel(const float4* __restrict__ X,
                                                        uint4* __restrict__ out)
{
    int idx = blockIdx.x * 256 + threadIdx.x;   // 8 floats each
    float4 a = X[idx * 2], b = X[idx * 2 + 1];
    __half2 h0 = __floats2half2_rn(a.x, a.y);
    __half2 h1 = __floats2half2_rn(a.z, a.w);
    __half2 h2 = __floats2half2_rn(b.x, b.y);
    __half2 h3 = __floats2half2_rn(b.z, b.w);
    out[idx] = make_uint4(*(uint32_t*)&h0, *(uint32_t*)&h1,
                          *(uint32_t*)&h2, *(uint32_t*)&h3);
}

// W [256][N] fp32 -> Wt [N][256] fp16
__global__ void __launch_bounds__(256) transpose_w_kernel(const float* __restrict__ W,
                                                          __half* __restrict__ Wt, int N)
{
    __shared__ float tile[32][33];
    int n0 = blockIdx.x * 32, k0 = blockIdx.y * 32;
    int tx = threadIdx.x & 31, ty = threadIdx.x >> 5;
    #pragma unroll
    for (int i = 0; i < 4; i++)
        tile[ty + i * 8][tx] = W[(k0 + ty + i * 8) * N + n0 + tx];
    __syncthreads();
    #pragma unroll
    for (int i = 0; i < 4; i++)
        Wt[(n0 + ty + i * 8) * 256 + k0 + tx] = __float2half_rn(tile[tx][ty + i * 8]);
}

// ---------------------------------------------------------------------------
// fp16 tensor-core GEMM: C[M,N] = A[M,256] @ Wt[N,256]^T
// block 128x128, K-chunks of 64, cp.async double buffer.
// PROJ=false: scatter to g_qh(scaled)/g_kh/g_vh.  PROJ=true: out = C + bias (fp32)
// ---------------------------------------------------------------------------
#define GS_ROW 9     // uint4 per smem row (8 data + 1 pad): LDSM conflict-free
#define GS_TILE (128 * GS_ROW)   // 1152 uint4 per tile
#define GS_BUF  (2 * GS_TILE)    // A + B per buffer

template<bool PROJ>
__global__ void __launch_bounds__(256) gemm_f16_kernel(
    const uint4* __restrict__ A4, const uint4* __restrict__ B4,
    float* __restrict__ outp, const float* __restrict__ bias)
{
    extern __shared__ uint4 smem4[];
    const int tid  = threadIdx.x;
    const int warp = tid >> 5, lane = tid & 31;
    const int g = lane >> 2, t = lane & 3;
    const int m0 = blockIdx.y * 128, n0 = blockIdx.x * 128;
    const int wm = warp >> 2, wn = warp & 3;    // 2x4 warps: 64 rows x 32 cols
    const uint32_t sb = smem_u32(smem4);
    const int arow = lane & 15, chi = lane >> 4;

    float acc[4][4][4];
    #pragma unroll
    for (int mt = 0; mt < 4; mt++)
        #pragma unroll
        for (int nt = 0; nt < 4; nt++)
            #pragma unroll
            for (int r = 0; r < 4; r++) acc[mt][nt][r] = 0.f;

    // async-load chunk c into buffer buf
    auto load_chunk = [&](int c, int buf) {
        #pragma unroll
        for (int i = 0; i < 4; i++) {
            int idx = i * 256 + tid;           // 1024 uint4 per tile
            int row = idx >> 3, cc = idx & 7;
            uint32_t da = sb + (uint32_t)(buf * GS_BUF + row * GS_ROW + cc) * 16;
            cp16(da, &A4[(long)(m0 + row) * 32 + c * 8 + cc]);
            uint32_t db = sb + (uint32_t)(buf * GS_BUF + GS_TILE + row * GS_ROW + cc) * 16;
            cp16(db, &B4[(long)(n0 + row) * 32 + c * 8 + cc]);
        }
        cp_commit();
    };

    load_chunk(0, 0);

    for (int c = 0; c < 4; c++) {
        cp_wait0();
        __syncthreads();
        if (c < 3) load_chunk(c + 1, (c + 1) & 1);
        const int bo = (c & 1) * GS_BUF;

        #pragma unroll
        for (int ks = 0; ks < 4; ks++) {
            uint32_t af[4][4];
            #pragma unroll
            for (int mt = 0; mt < 4; mt++)
                ldsm4(af[mt], sb + (uint32_t)(bo + (wm * 64 + mt * 16 + arow) * GS_ROW
                                              + ks * 2 + chi) * 16);
            uint32_t bf[2][4];
            #pragma unroll
            for (int np = 0; np < 2; np++)
                ldsm4(bf[np], sb + (uint32_t)(bo + GS_TILE
                                              + (wn * 32 + np * 16 + arow) * GS_ROW
                                              + ks * 2 + chi) * 16);
            #pragma unroll
            for (int mt = 0; mt < 4; mt++)
                #pragma unroll
                for (int nt = 0; nt < 4; nt++) {
                    uint32_t bb[2] = { bf[nt >> 1][nt & 1], bf[nt >> 1][(nt & 1) + 2] };
                    mma_f16(acc[mt][nt], af[mt], bb);
                }
        }
        __syncthreads();
    }

    if (PROJ) {
        #pragma unroll
        for (int mt = 0; mt < 4; mt++) {
            int m = m0 + wm * 64 + mt * 16 + g;
            #pragma unroll
            for (int nt = 0; nt < 4; nt++) {
                int col = n0 + wn * 32 + nt * 8 + 2 * t;
                float b0 = bias[col], b1 = bias[col + 1];
                *(float2*)&outp[(long)m * 256 + col] =
                    make_float2(acc[mt][nt][0] + b0, acc[mt][nt][1] + b1);
                *(float2*)&outp[(long)(m + 8) * 256 + col] =
                    make_float2(acc[mt][nt][2] + b0, acc[mt][nt][3] + b1);
            }
        }
    } else {
        const float scale = 0.17677669529663687f;   // 32^-0.5 folded into q
        #pragma unroll
        for (int mt = 0; mt < 4; mt++) {
            int m = m0 + wm * 64 + mt * 16 + g;
            int bb = m >> 10, nn = m & 1023;
            #pragma unroll
            for (int nt = 0; nt < 4; nt++) {
                int col = n0 + wn * 32 + nt * 8 + 2 * t;
                int sel = col >> 8, hh = (col >> 5) & 7, dd = col & 31;
                float c0 = acc[mt][nt][0], c1 = acc[mt][nt][1];
                float c2 = acc[mt][nt][2], c3 = acc[mt][nt][3];
                if (sel == 0) { c0 *= scale; c1 *= scale; c2 *= scale; c3 *= scale; }
                __half* dst = (sel == 0) ? g_qh : (sel == 1) ? g_kh : g_vh;
                long base = (((long)bb * HH + hh) * NN + nn) * HD + dd;
                *(__half2*)&dst[base]           = __floats2half2_rn(c0, c1);
                *(__half2*)&dst[base + 8 * HD]  = __floats2half2_rn(c2, c3);
            }
        }
    }
}

// ---------------------------------------------------------------------------
// Fused flash attention, fp16 mma.m16n8k16 (unchanged core from R3),
// epilogue now writes fp16 g_xh.
// ---------------------------------------------------------------------------
#define KP_STRIDE 40

__global__ void __launch_bounds__(256, 2) attn_mma_kernel(
    const int* __restrict__ rp, const int* __restrict__ rel_len,
    const float* __restrict__ bias_table)
{
    extern __shared__ uint32_t sm[];
    uint32_t* kp_s = sm;
    uint32_t* vp_s = kp_s + 8 * 16 * KP_STRIDE;
    int*      rp_s = (int*)(vp_s + 8 * 16 * KP_STRIDE);

    const int tid  = threadIdx.x;
    const int h    = tid >> 5;
    const int lane = tid & 31;
    const int g    = lane >> 2;
    const int t    = lane & 3;
    const int b    = blockIdx.x >> 5;
    const int row0 = (blockIdx.x & 31) * 32;

    const int mask_len = (int)(__int2float_rn(rel_len[b]) * 0.5f);
    float bt2 = 0.f;
    if (lane < TABLE)
        bt2 = bias_table[lane * HH + h] + ((lane > mask_len) ? -100.f : 0.f);

    uint32_t qa[2][2][4];
    {
        const uint32_t* qw = (const uint32_t*)g_qh;
        long rbase = ((long)(b * HH) + h) * NN + row0;
        #pragma unroll
        for (int mt = 0; mt < 2; mt++) {
            long rA = (rbase + mt * 16 + g) * 16;
            long rB = rA + 8 * 16;
            #pragma unroll
            for (int ks = 0; ks < 2; ks++) {
                int w = ks * 8 + t;
                qa[mt][ks][0] = qw[rA + w];
                qa[mt][ks][1] = qw[rB + w];
                qa[mt][ks][2] = qw[rA + w + 4];
                qa[mt][ks][3] = qw[rB + w + 4];
            }
        }
    }

    float o[2][4][4];
    #pragma unroll
    for (int mt = 0; mt < 2; mt++)
        #pragma unroll
        for (int nt = 0; nt < 4; nt++)
            #pragma unroll
            for (int r = 0; r < 4; r++) o[mt][nt][r] = 0.f;
    float mrow[2][2] = {{-1e30f, -1e30f}, {-1e30f, -1e30f}};
    float lrow[2][2] = {{0.f, 0.f}, {0.f, 0.f}};

    const uint32_t* kh = &kp_s[h * 16 * KP_STRIDE];
    const uint32_t* vh = &vp_s[h * 16 * KP_STRIDE];
    const __half* gk = g_kh;
    const __half* gv = g_vh;

    for (int j0 = 0; j0 < NN; j0 += 32) {
        __syncthreads();
        #pragma unroll
        for (int it = 0; it < 4; it++) {
            int idx = it * 256 + tid;
            int key = idx & 31;
            int q4  = (idx >> 5) & 3;
            int h2  = idx >> 7;
            long base = (((long)(b * HH + h2)) * NN + j0 + key) * 32;
            uint4 kw = *(const uint4*)(gk + base + q4 * 8);
            uint32_t* col = &kp_s[h2 * (16 * KP_STRIDE) + (q4 * 4) * KP_STRIDE + key];
            col[0 * KP_STRIDE] = kw.x;
            col[1 * KP_STRIDE] = kw.y;
            col[2 * KP_STRIDE] = kw.z;
            col[3 * KP_STRIDE] = kw.w;
        }
        #pragma unroll
        for (int it = 0; it < 2; it++) {
            int idx = it * 256 + tid;
            int d4   = idx & 3;
            int key2 = (idx >> 2) & 15;
            int h2   = idx >> 6;
            long base = (((long)(b * HH + h2)) * NN + j0 + 2 * key2) * 32;
            uint4 v0 = *(const uint4*)(gv + base + d4 * 8);
            uint4 v1 = *(const uint4*)(gv + base + 32 + d4 * 8);
            uint32_t* dst = &vp_s[h2 * (16 * KP_STRIDE) + key2 * KP_STRIDE + d4 * 8];
            *(uint4*)dst = make_uint4(
                prmt(v0.x, v1.x, 0x5410), prmt(v0.x, v1.x, 0x7632),
                prmt(v0.y, v1.y, 0x5410), prmt(v0.y, v1.y, 0x7632));
            *(uint4*)(dst + 4) = make_uint4(
                prmt(v0.z, v1.z, 0x5410), prmt(v0.z, v1.z, 0x7632),
                prmt(v0.w, v1.w, 0x5410), prmt(v0.w, v1.w, 0x7632));
        }
        {
            int rr = tid >> 3, cc = (tid & 7) * 4;
            int4 rv = *(const int4*)&rp[((long)b * NN + row0 + rr) * NN + j0 + cc];
            rp_s[rr * 33 + cc + 0] = rv.x;
            rp_s[rr * 33 + cc + 1] = rv.y;
            rp_s[rr * 33 + cc + 2] = rv.z;
            rp_s[rr * 33 + cc + 3] = rv.w;
        }
        __syncthreads();

        float c[2][4][4];
        #pragma unroll
        for (int mt = 0; mt < 2; mt++)
            #pragma unroll
            for (int nt = 0; nt < 4; nt++)
                #pragma unroll
                for (int r = 0; r < 4; r++) c[mt][nt][r] = 0.f;

        #pragma unroll
        for (int nt = 0; nt < 4; nt++)
            #pragma unroll
            for (int ks = 0; ks < 2; ks++) {
                uint32_t bf[2];
                bf[0] = kh[(ks * 8 + t) * KP_STRIDE + nt * 8 + g];
                bf[1] = kh[(ks * 8 + t + 4) * KP_STRIDE + nt * 8 + g];
                mma_f16(c[0][nt], qa[0][ks], bf);
                mma_f16(c[1][nt], qa[1][ks], bf);
            }

        #pragma unroll
        for (int mt = 0; mt < 2; mt++) {
            int rA = mt * 16 + g;
            int rB = rA + 8;
            float mx0 = -1e30f, mx1 = -1e30f;
            #pragma unroll
            for (int nt = 0; nt < 4; nt++) {
                int colb = nt * 8 + 2 * t;
                int r00 = rp_s[rA * 33 + colb], r01 = rp_s[rA * 33 + colb + 1];
                int r10 = rp_s[rB * 33 + colb], r11 = rp_s[rB * 33 + colb + 1];
                c[mt][nt][0] += __shfl_sync(0xffffffffu, bt2, r00);
                c[mt][nt][1] += __shfl_sync(0xffffffffu, bt2, r01);
                c[mt][nt][2] += __shfl_sync(0xffffffffu, bt2, r10);
                c[mt][nt][3] += __shfl_sync(0xffffffffu, bt2, r11);
                mx0 = fmaxf(mx0, fmaxf(c[mt][nt][0], c[mt][nt][1]));
                mx1 = fmaxf(mx1, fmaxf(c[mt][nt][2], c[mt][nt][3]));
            }
            mx0 = fmaxf(mx0, __shfl_xor_sync(0xffffffffu, mx0, 1));
            mx0 = fmaxf(mx0, __shfl_xor_sync(0xffffffffu, mx0, 2));
            mx1 = fmaxf(mx1, __shfl_xor_sync(0xffffffffu, mx1, 1));
            mx1 = fmaxf(mx1, __shfl_xor_sync(0xffffffffu, mx1, 2));

            float nm0 = fmaxf(mrow[mt][0], mx0);
            float nm1 = fmaxf(mrow[mt][1], mx1);
            float corr0 = __expf(mrow[mt][0] - nm0);
            float corr1 = __expf(mrow[mt][1] - nm1);
            float rs0 = 0.f, rs1 = 0.f;
            #pragma unroll
            for (int nt = 0; nt < 4; nt++) {
                c[mt][nt][0] = __expf(c[mt][nt][0] - nm0);
                c[mt][nt][1] = __expf(c[mt][nt][1] - nm0);
                c[mt][nt][2] = __expf(c[mt][nt][2] - nm1);
                c[mt][nt][3] = __expf(c[mt][nt][3] - nm1);
                rs0 += c[mt][nt][0] + c[mt][nt][1];
                rs1 += c[mt][nt][2] + c[mt][nt][3];
            }
            rs0 += __shfl_xor_sync(0xffffffffu, rs0, 1);
            rs0 += __shfl_xor_sync(0xffffffffu, rs0, 2);
            rs1 += __shfl_xor_sync(0xffffffffu, rs1, 1);
            rs1 += __shfl_xor_sync(0xffffffffu, rs1, 2);
            lrow[mt][0] = lrow[mt][0] * corr0 + rs0;
            lrow[mt][1] = lrow[mt][1] * corr1 + rs1;
            #pragma unroll
            for (int nt = 0; nt < 4; nt++) {
                o[mt][nt][0] *= corr0; o[mt][nt][1] *= corr0;
                o[mt][nt][2] *= corr1; o[mt][nt][3] *= corr1;
            }
            mrow[mt][0] = nm0;
            mrow[mt][1] = nm1;
        }

        uint32_t pa[2][2][4];
        #pragma unroll
        for (int mt = 0; mt < 2; mt++)
            #pragma unroll
            for (int ks = 0; ks < 2; ks++) {
                pa[mt][ks][0] = h2pack(c[mt][2*ks  ][0], c[mt][2*ks  ][1]);
                pa[mt][ks][1] = h2pack(c[mt][2*ks  ][2], c[mt][2*ks  ][3]);
                pa[mt][ks][2] = h2pack(c[mt][2*ks+1][0], c[mt][2*ks+1][1]);
                pa[mt][ks][3] = h2pack(c[mt][2*ks+1][2], c[mt][2*ks+1][3]);
            }

        #pragma unroll
        for (int ks = 0; ks < 2; ks++)
            #pragma unroll
            for (int nt = 0; nt < 4; nt++) {
                uint32_t bf[2];
                bf[0] = vh[(ks * 8 + t) * KP_STRIDE + nt * 8 + g];
                bf[1] = vh[(ks * 8 + t + 4) * KP_STRIDE + nt * 8 + g];
                mma_f16(o[0][nt], pa[0][ks], bf);
                mma_f16(o[1][nt], pa[1][ks], bf);
            }
    }

    // epilogue: normalize, store fp16 to g_xh (A-matrix layout for proj GEMM)
    #pragma unroll
    for (int mt = 0; mt < 2; mt++) {
        float i0 = 1.f / lrow[mt][0];
        float i1 = 1.f / lrow[mt][1];
        int rA = row0 + mt * 16 + g;
        #pragma unroll
        for (int nt = 0; nt < 4; nt++) {
            int col = h * HD + nt * 8 + 2 * t;
            *(__half2*)&g_xh[((long)b * NN + rA) * CC + col] =
                __floats2half2_rn(o[mt][nt][0] * i0, o[mt][nt][1] * i0);
            *(__half2*)&g_xh[((long)b * NN + rA + 8) * CC + col] =
                __floats2half2_rn(o[mt][nt][2] * i1, o[mt][nt][3] * i1);
        }
    }
}

// ---------------------------------------------------------------------------
extern "C" void kernel_launch(void* const* d_in, const int* in_sizes, int n_in,
                              void* d_out, int out_size)
{
    const float* X       = (const float*)d_in[0];
    const int*   rp      = (const int*)  d_in[1];
    const int*   rel_len = (const int*)  d_in[2];
    const float* Wqkv    = (const float*)d_in[3];
    const float* Wproj   = (const float*)d_in[4];
    const float* bproj   = (const float*)d_in[5];
    const float* btab    = (const float*)d_in[6];
    float* out = (float*)d_out;

    __half* d_ah;   cudaGetSymbolAddress((void**)&d_ah,  g_ah);
    __half* d_wqt;  cudaGetSymbolAddress((void**)&d_wqt, g_wqt);
    __half* d_wpt;  cudaGetSymbolAddress((void**)&d_wpt, g_wpt);

    const int gemm_smem = 2 * GS_BUF * 16;   // 73728 B

    // converts
    convert_x_kernel<<<1024, 256>>>((const float4*)X, (uint4*)d_ah);
    transpose_w_kernel<<<dim3(24, 8), 256>>>(Wqkv,  d_wqt, 768);
    transpose_w_kernel<<<dim3(8, 8),  256>>>(Wproj, d_wpt, 256);

    // qkv GEMM (fp16 MMA)
    cudaFuncSetAttribute(gemm_f16_kernel<false>,
                         cudaFuncAttributeMaxDynamicSharedMemorySize, gemm_smem);
    gemm_f16_kernel<false><<<dim3(6, 64), 256, gemm_smem>>>(
        (const uint4*)d_ah, (const uint4*)d_wqt, nullptr, nullptr);

    // attention
    {
        const int smem_bytes = (8*16*KP_STRIDE * 2) * 4 + 32*33*4;
        cudaFuncSetAttribute(attn_mma_kernel,
                             cudaFuncAttributeMaxDynamicSharedMemorySize, smem_bytes);
        attn_mma_kernel<<<BB * 32, 256, smem_bytes>>>(rp, rel_len, btab);
    }

    // proj GEMM (fp16 MMA) + bias -> fp32 out
    cudaFuncSetAttribute(gemm_f16_kernel<true>,
                         cudaFuncAttributeMaxDynamicSharedMemorySize, gemm_smem);
    __half* d_xh;  cudaGetSymbolAddress((void**)&d_xh, g_xh);
    gemm_f16_kernel<true><<<dim3(2, 64), 256, gemm_smem>>>(
        (const uint4*)d_xh, (const uint4*)d_wpt, out, bproj);
}

// round 7
// speedup vs baseline: 1.3495x; 1.3495x over previous
#include <cuda_runtime.h>
#include <cuda_fp16.h>
#include <cstdint>

#define BB 8
#define NN 1024
#define CC 256
#define HH 8
#define HD 32
#define TABLE 10

// Scratch (allocation-free rule: __device__ globals)
__device__ __half g_ah [BB*NN*CC];      // X in fp16, row-major [8192][256]
__device__ __half g_wqt[3*CC*CC];       // W_qkv^T fp16 [768][256]
__device__ __half g_wpt[CC*CC];         // W_proj^T fp16 [256][256]
__device__ __half g_qh [BB*HH*NN*HD];   // q * scale * log2e, fp16
__device__ __half g_kh [BB*HH*NN*HD];
__device__ __half g_vh [BB*HH*NN*HD];
__device__ __half g_xh [BB*NN*CC];      // attention output fp16 [8192][256]

// ---------------------------------------------------------------------------
// helpers
// ---------------------------------------------------------------------------
__device__ __forceinline__ void mma_f16(float* c, const uint32_t* a, const uint32_t* b) {
    asm volatile(
        "mma.sync.aligned.m16n8k16.row.col.f32.f16.f16.f32 "
        "{%0,%1,%2,%3},{%4,%5,%6,%7},{%8,%9},{%0,%1,%2,%3};\n"
        : "+f"(c[0]), "+f"(c[1]), "+f"(c[2]), "+f"(c[3])
        : "r"(a[0]), "r"(a[1]), "r"(a[2]), "r"(a[3]), "r"(b[0]), "r"(b[1]));
}
__device__ __forceinline__ void ldsm4(uint32_t* r, uint32_t addr) {
    asm volatile("ldmatrix.sync.aligned.m8n8.x4.shared.b16 {%0,%1,%2,%3},[%4];"
                 : "=r"(r[0]), "=r"(r[1]), "=r"(r[2]), "=r"(r[3]) : "r"(addr));
}
__device__ __forceinline__ void ldsm4t(uint32_t* r, uint32_t addr) {
    asm volatile("ldmatrix.sync.aligned.m8n8.x4.trans.shared.b16 {%0,%1,%2,%3},[%4];"
                 : "=r"(r[0]), "=r"(r[1]), "=r"(r[2]), "=r"(r[3]) : "r"(addr));
}
__device__ __forceinline__ uint32_t smem_u32(const void* p) {
    uint32_t a;
    asm("{ .reg .u64 t; cvta.to.shared.u64 t, %1; cvt.u32.u64 %0, t; }" : "=r"(a) : "l"(p));
    return a;
}
__device__ __forceinline__ void cp16(uint32_t dst, const void* src) {
    asm volatile("cp.async.ca.shared.global [%0],[%1],16;" :: "r"(dst), "l"(src));
}
__device__ __forceinline__ void cp_commit() { asm volatile("cp.async.commit_group;"); }
__device__ __forceinline__ void cp_wait0()  { asm volatile("cp.async.wait_group 0;"); }
__device__ __forceinline__ void cp_wait1()  { asm volatile("cp.async.wait_group 1;"); }
__device__ __forceinline__ uint32_t ex2h2(uint32_t x) {
    uint32_t r;
    asm("ex2.approx.f16x2 %0, %1;" : "=r"(r) : "r"(x));
    return r;
}
__device__ __forceinline__ uint32_t hmax2u(uint32_t a, uint32_t b) {
    __half2 r = __hmax2(*(__half2*)&a, *(__half2*)&b);
    return *(uint32_t*)&r;
}
__device__ __forceinline__ uint32_t hsub2u(uint32_t a, uint32_t b) {
    __half2 r = __hsub2(*(__half2*)&a, *(__half2*)&b);
    return *(uint32_t*)&r;
}
__device__ __forceinline__ uint32_t h2swap(uint32_t a) {
    __half2 r = __lowhigh2highlow(*(__half2*)&a);
    return *(uint32_t*)&r;
}
__device__ __forceinline__ uint32_t pack2(float lo, float hi) {
    __half2 h = __floats2half2_rn(lo, hi);
    return *(uint32_t*)&h;
}

// ---------------------------------------------------------------------------
// Conversions
// ---------------------------------------------------------------------------
__global__ void __launch_bounds__(256) convert_x_kernel(const float4* __restrict__ X,
                                                        uint4* __restrict__ out)
{
    int idx = blockIdx.x * 256 + threadIdx.x;
    float4 a = X[idx * 2], b = X[idx * 2 + 1];
    __half2 h0 = __floats2half2_rn(a.x, a.y);
    __half2 h1 = __floats2half2_rn(a.z, a.w);
    __half2 h2 = __floats2half2_rn(b.x, b.y);
    __half2 h3 = __floats2half2_rn(b.z, b.w);
    out[idx] = make_uint4(*(uint32_t*)&h0, *(uint32_t*)&h1,
                          *(uint32_t*)&h2, *(uint32_t*)&h3);
}

__global__ void __launch_bounds__(256) transpose_w_kernel(const float* __restrict__ W,
                                                          __half* __restrict__ Wt, int N)
{
    __shared__ float tile[32][33];
    int n0 = blockIdx.x * 32, k0 = blockIdx.y * 32;
    int tx = threadIdx.x & 31, ty = threadIdx.x >> 5;
    #pragma unroll
    for (int i = 0; i < 4; i++)
        tile[ty + i * 8][tx] = W[(k0 + ty + i * 8) * N + n0 + tx];
    __syncthreads();
    #pragma unroll
    for (int i = 0; i < 4; i++)
        Wt[(n0 + ty + i * 8) * 256 + k0 + tx] = __float2half_rn(tile[tx][ty + i * 8]);
}

// ---------------------------------------------------------------------------
// fp16 tensor-core GEMM: C[M,N] = A[M,256] @ Wt[N,256]^T  (unchanged from R6)
// ---------------------------------------------------------------------------
#define GS_ROW 9
#define GS_TILE (128 * GS_ROW)
#define GS_BUF  (2 * GS_TILE)

template<bool PROJ>
__global__ void __launch_bounds__(256) gemm_f16_kernel(
    const uint4* __restrict__ A4, const uint4* __restrict__ B4,
    float* __restrict__ outp, const float* __restrict__ bias)
{
    extern __shared__ uint4 smem4[];
    const int tid  = threadIdx.x;
    const int warp = tid >> 5, lane = tid & 31;
    const int g = lane >> 2, t = lane & 3;
    const int m0 = blockIdx.y * 128, n0 = blockIdx.x * 128;
    const int wm = warp >> 2, wn = warp & 3;
    const uint32_t sb = smem_u32(smem4);
    const int arow = lane & 15, chi = lane >> 4;

    float acc[4][4][4];
    #pragma unroll
    for (int mt = 0; mt < 4; mt++)
        #pragma unroll
        for (int nt = 0; nt < 4; nt++)
            #pragma unroll
            for (int r = 0; r < 4; r++) acc[mt][nt][r] = 0.f;

    auto load_chunk = [&](int c, int buf) {
        #pragma unroll
        for (int i = 0; i < 4; i++) {
            int idx = i * 256 + tid;
            int row = idx >> 3, cc = idx & 7;
            uint32_t da = sb + (uint32_t)(buf * GS_BUF + row * GS_ROW + cc) * 16;
            cp16(da, &A4[(long)(m0 + row) * 32 + c * 8 + cc]);
            uint32_t db = sb + (uint32_t)(buf * GS_BUF + GS_TILE + row * GS_ROW + cc) * 16;
            cp16(db, &B4[(long)(n0 + row) * 32 + c * 8 + cc]);
        }
        cp_commit();
    };

    load_chunk(0, 0);

    for (int c = 0; c < 4; c++) {
        cp_wait0();
        __syncthreads();
        if (c < 3) load_chunk(c + 1, (c + 1) & 1);
        const int bo = (c & 1) * GS_BUF;

        #pragma unroll
        for (int ks = 0; ks < 4; ks++) {
            uint32_t af[4][4];
            #pragma unroll
            for (int mt = 0; mt < 4; mt++)
                ldsm4(af[mt], sb + (uint32_t)(bo + (wm * 64 + mt * 16 + arow) * GS_ROW
                                              + ks * 2 + chi) * 16);
            uint32_t bf[2][4];
            #pragma unroll
            for (int np = 0; np < 2; np++)
                ldsm4(bf[np], sb + (uint32_t)(bo + GS_TILE
                                              + (wn * 32 + np * 16 + arow) * GS_ROW
                                              + ks * 2 + chi) * 16);
            #pragma unroll
            for (int mt = 0; mt < 4; mt++)
                #pragma unroll
                for (int nt = 0; nt < 4; nt++) {
                    uint32_t bb[2] = { bf[nt >> 1][nt & 1], bf[nt >> 1][(nt & 1) + 2] };
                    mma_f16(acc[mt][nt], af[mt], bb);
                }
        }
        __syncthreads();
    }

    if (PROJ) {
        #pragma unroll
        for (int mt = 0; mt < 4; mt++) {
            int m = m0 + wm * 64 + mt * 16 + g;
            #pragma unroll
            for (int nt = 0; nt < 4; nt++) {
                int col = n0 + wn * 32 + nt * 8 + 2 * t;
                float b0 = bias[col], b1 = bias[col + 1];
                *(float2*)&outp[(long)m * 256 + col] =
                    make_float2(acc[mt][nt][0] + b0, acc[mt][nt][1] + b1);
                *(float2*)&outp[(long)(m + 8) * 256 + col] =
                    make_float2(acc[mt][nt][2] + b0, acc[mt][nt][3] + b1);
            }
        }
    } else {
        // scale = 32^-0.5 * log2(e), folded into q for the ex2-domain softmax
        const float scale = 0.25503483f;
        #pragma unroll
        for (int mt = 0; mt < 4; mt++) {
            int m = m0 + wm * 64 + mt * 16 + g;
            int bb = m >> 10, nn = m & 1023;
            #pragma unroll
            for (int nt = 0; nt < 4; nt++) {
                int col = n0 + wn * 32 + nt * 8 + 2 * t;
                int sel = col >> 8, hh = (col >> 5) & 7, dd = col & 31;
                float c0 = acc[mt][nt][0], c1 = acc[mt][nt][1];
                float c2 = acc[mt][nt][2], c3 = acc[mt][nt][3];
                if (sel == 0) { c0 *= scale; c1 *= scale; c2 *= scale; c3 *= scale; }
                __half* dst = (sel == 0) ? g_qh : (sel == 1) ? g_kh : g_vh;
                long base = (((long)bb * HH + hh) * NN + nn) * HD + dd;
                *(__half2*)&dst[base]           = __floats2half2_rn(c0, c1);
                *(__half2*)&dst[base + 8 * HD]  = __floats2half2_rn(c2, c3);
            }
        }
    }
}

// ---------------------------------------------------------------------------
// Fused flash attention v2:
//   raw K/V layout + ldmatrix(.trans) frags, cp.async double buffer,
//   ex2.f16x2 softmax in log2-domain, ones-column row sums.
// Block = (batch, 32 query rows), 8 warps = 8 heads.
// ---------------------------------------------------------------------------
#define KROWB   80                      // bytes per K/V row (32 halves + pad -> 20 words)
#define HEADB   (32 * KROWB)            // 2560 B per head tile
#define VOFF    (8 * HEADB)             // 20480
#define RPOFF   (2 * 8 * HEADB)         // 40960
#define RPROWB  144                     // 32 ints + pad, 16B aligned
#define BUFB    (RPOFF + 32 * RPROWB)   // 45568 per stage
#define ATT_SMEM (2 * BUFB)             // 91136

__global__ void __launch_bounds__(256, 2) attn_mma_kernel(
    const int* __restrict__ rp, const int* __restrict__ rel_len,
    const float* __restrict__ bias_table)
{
    extern __shared__ char smc[];
    const uint32_t sb = smem_u32(smc);

    const int tid  = threadIdx.x;
    const int h    = tid >> 5;
    const int lane = tid & 31;
    const int g    = lane >> 2;
    const int t    = lane & 3;
    const int b    = blockIdx.x >> 5;
    const int row0 = (blockIdx.x & 31) * 32;

    // per-head masked bias table (log2 domain), lane registers for shfl lookup
    const int mask_len = (int)(__int2float_rn(rel_len[b]) * 0.5f);
    float bt2 = 0.f;
    if (lane < TABLE)
        bt2 = bias_table[lane * HH + h] * 1.4426950408889634f
            + ((lane > mask_len) ? -144.2695040888963f : 0.f);

    // ---- one-time: fill V pad columns (d=32..39) with fp16 ones, both buffers ----
    {
        const uint4 ones = make_uint4(0x3C003C00u, 0x3C003C00u, 0x3C003C00u, 0x3C003C00u);
        #pragma unroll
        for (int i = 0; i < 2; i++) {
            int row = tid + i * 256;           // 512 rows: [buf][h][key]
            int buf = row >> 8, rem = row & 255;
            *(uint4*)(smc + buf * BUFB + VOFF + rem * KROWB + 64) = ones;
        }
    }

    // ---- Q fragments (log2e*scale pre-folded) ----
    uint32_t qa[2][2][4];
    {
        const uint32_t* qw = (const uint32_t*)g_qh;
        long rbase = ((long)(b * HH) + h) * NN + row0;
        #pragma unroll
        for (int mt = 0; mt < 2; mt++) {
            long rA = (rbase + mt * 16 + g) * 16;
            long rB = rA + 8 * 16;
            #pragma unroll
            for (int ks = 0; ks < 2; ks++) {
                int w = ks * 8 + t;
                qa[mt][ks][0] = qw[rA + w];
                qa[mt][ks][1] = qw[rB + w];
                qa[mt][ks][2] = qw[rA + w + 4];
                qa[mt][ks][3] = qw[rB + w + 4];
            }
        }
    }

    float o[2][5][4];                       // nt=4 is the ones column (row sums)
    #pragma unroll
    for (int mt = 0; mt < 2; mt++)
        #pragma unroll
        for (int nt = 0; nt < 5; nt++)
            #pragma unroll
            for (int r = 0; r < 4; r++) o[mt][nt][r] = 0.f;
    uint32_t moldA[2], moldB[2];
    {
        uint32_t m0 = pack2(-300.f, -300.f);
        moldA[0] = moldA[1] = moldB[0] = moldB[1] = m0;
    }

    const __half* gk = g_kh;
    const __half* gv = g_vh;

    auto prefetch = [&](int j, int buf) {
        uint32_t base = sb + buf * BUFB;
        long kvbase = (((long)b * HH) * NN + j * 32) * HD;
        #pragma unroll
        for (int i = 0; i < 4; i++) {
            int idx = i * 256 + tid;                 // 1024: [h][key][chunk]
            int ch = idx & 3, key = (idx >> 2) & 31, h2 = idx >> 7;
            long src = kvbase + (long)h2 * (NN * HD) + key * HD + ch * 8;
            uint32_t d = base + h2 * HEADB + key * KROWB + ch * 16;
            cp16(d, gk + src);
            cp16(d + VOFF, gv + src);
        }
        {
            int r = tid >> 3, ch = tid & 7;
            cp16(base + RPOFF + r * RPROWB + ch * 16,
                 rp + ((long)b * NN + row0 + r) * NN + j * 32 + ch * 4);
        }
        cp_commit();
    };

    prefetch(0, 0);

    const int ln8 = lane & 7, l8 = lane >> 3;

    for (int j = 0; j < 32; j++) {
        const int buf = j & 1;
        __syncthreads();                       // everyone done reading buf^1
        if (j + 1 < 32) { prefetch(j + 1, buf ^ 1); cp_wait1(); }
        else            { cp_wait0(); }
        __syncthreads();

        const uint32_t bo  = sb + buf * BUFB;
        const uint32_t kha = bo + h * HEADB;
        const uint32_t vha = kha + VOFF;
        const char*    rpb = smc + buf * BUFB + RPOFF;

        // ---- S = Q @ K^T ----
        float c[2][4][4];
        #pragma unroll
        for (int mt = 0; mt < 2; mt++)
            #pragma unroll
            for (int nt = 0; nt < 4; nt++)
                #pragma unroll
                for (int r = 0; r < 4; r++) c[mt][nt][r] = 0.f;
        {
            uint32_t kb[4][4];
            uint32_t ka = kha + (uint32_t)(ln8 * KROWB + l8 * 16);
            #pragma unroll
            for (int nt = 0; nt < 4; nt++)
                ldsm4(kb[nt], ka + nt * (8 * KROWB));
            #pragma unroll
            for (int nt = 0; nt < 4; nt++)
                #pragma unroll
                for (int ks = 0; ks < 2; ks++) {
                    uint32_t bf[2] = { kb[nt][2 * ks], kb[nt][2 * ks + 1] };
                    mma_f16(c[0][nt], qa[0][ks], bf);
                    mma_f16(c[1][nt], qa[1][ks], bf);
                }
        }

        // ---- bias (f32) + fp16 online softmax -> P A-frags ----
        uint32_t pa[2][2][4];
        #pragma unroll
        for (int mt = 0; mt < 2; mt++) {
            int rA = mt * 16 + g, rB = rA + 8;
            #pragma unroll
            for (int nt = 0; nt < 4; nt++) {
                int colb = nt * 8 + 2 * t;
                int2 ra = *(const int2*)(rpb + rA * RPROWB + colb * 4);
                int2 rb = *(const int2*)(rpb + rB * RPROWB + colb * 4);
                c[mt][nt][0] += __shfl_sync(0xffffffffu, bt2, ra.x);
                c[mt][nt][1] += __shfl_sync(0xffffffffu, bt2, ra.y);
                c[mt][nt][2] += __shfl_sync(0xffffffffu, bt2, rb.x);
                c[mt][nt][3] += __shfl_sync(0xffffffffu, bt2, rb.y);
            }
            uint32_t hA[4], hB[4];
            #pragma unroll
            for (int nt = 0; nt < 4; nt++) {
                hA[nt] = pack2(c[mt][nt][0], c[mt][nt][1]);
                hB[nt] = pack2(c[mt][nt][2], c[mt][nt][3]);
            }
            uint32_t mA = hmax2u(hmax2u(hA[0], hA[1]), hmax2u(hA[2], hA[3]));
            uint32_t mB = hmax2u(hmax2u(hB[0], hB[1]), hmax2u(hB[2], hB[3]));
            mA = hmax2u(mA, h2swap(mA));
            mB = hmax2u(mB, h2swap(mB));
            mA = hmax2u(mA, __shfl_xor_sync(0xffffffffu, mA, 1));
            mA = hmax2u(mA, __shfl_xor_sync(0xffffffffu, mA, 2));
            mB = hmax2u(mB, __shfl_xor_sync(0xffffffffu, mB, 1));
            mB = hmax2u(mB, __shfl_xor_sync(0xffffffffu, mB, 2));

            uint32_t nmA = hmax2u(moldA[mt], mA);
            uint32_t nmB = hmax2u(moldB[mt], mB);
            float corrA = __low2float(*(__half2*)&(uint32_t&)*(&(nmA)) ) ; // placeholder
            {
                uint32_t cA = ex2h2(hsub2u(moldA[mt], nmA));
                uint32_t cB = ex2h2(hsub2u(moldB[mt], nmB));
                corrA = __low2float(*(__half2*)&cA);
                float corrB = __low2float(*(__half2*)&cB);
                moldA[mt] = nmA; moldB[mt] = nmB;
                #pragma unroll
                for (int nt = 0; nt < 4; nt++) {
                    hA[nt] = ex2h2(hsub2u(hA[nt], nmA));
                    hB[nt] = ex2h2(hsub2u(hB[nt], nmB));
                }
                #pragma unroll
                for (int nt = 0; nt < 5; nt++) {
                    o[mt][nt][0] *= corrA; o[mt][nt][1] *= corrA;
                    o[mt][nt][2] *= corrB; o[mt][nt][3] *= corrB;
                }
            }
            #pragma unroll
            for (int ks = 0; ks < 2; ks++) {
                pa[mt][ks][0] = hA[2 * ks];
                pa[mt][ks][1] = hB[2 * ks];
                pa[mt][ks][2] = hA[2 * ks + 1];
                pa[mt][ks][3] = hB[2 * ks + 1];
            }
        }

        // ---- O += P @ [V | 1] ----
        {
            uint32_t vb[5][4];
            uint32_t va = vha + (uint32_t)(lane * KROWB);
            #pragma unroll
            for (int nt = 0; nt < 5; nt++)
                ldsm4t(vb[nt], va + nt * 16);
            #pragma unroll
            for (int ks = 0; ks < 2; ks++)
                #pragma unroll
                for (int nt = 0; nt < 5; nt++) {
                    uint32_t bf[2] = { vb[nt][2 * ks], vb[nt][2 * ks + 1] };
                    mma_f16(o[0][nt], pa[0][ks], bf);
                    mma_f16(o[1][nt], pa[1][ks], bf);
                }
        }
    }

    // ---- epilogue: normalize by ones-column sums, store fp16 to g_xh ----
    #pragma unroll
    for (int mt = 0; mt < 2; mt++) {
        float i0 = 1.f / o[mt][4][0];
        float i1 = 1.f / o[mt][4][2];
        int rA = row0 + mt * 16 + g;
        #pragma unroll
        for (int nt = 0; nt < 4; nt++) {
            int col = h * HD + nt * 8 + 2 * t;
            *(__half2*)&g_xh[((long)b * NN + rA) * CC + col] =
                __floats2half2_rn(o[mt][nt][0] * i0, o[mt][nt][1] * i0);
            *(__half2*)&g_xh[((long)b * NN + rA + 8) * CC + col] =
                __floats2half2_rn(o[mt][nt][2] * i1, o[mt][nt][3] * i1);
        }
    }
}

// ---------------------------------------------------------------------------
extern "C" void kernel_launch(void* const* d_in, const int* in_sizes, int n_in,
                              void* d_out, int out_size)
{
    const float* X       = (const float*)d_in[0];
    const int*   rp      = (const int*)  d_in[1];
    const int*   rel_len = (const int*)  d_in[2];
    const float* Wqkv    = (const float*)d_in[3];
    const float* Wproj   = (const float*)d_in[4];
    const float* bproj   = (const float*)d_in[5];
    const float* btab    = (const float*)d_in[6];
    float* out = (float*)d_out;

    __half* d_ah;   cudaGetSymbolAddress((void**)&d_ah,  g_ah);
    __half* d_wqt;  cudaGetSymbolAddress((void**)&d_wqt, g_wqt);
    __half* d_wpt;  cudaGetSymbolAddress((void**)&d_wpt, g_wpt);
    __half* d_xh;   cudaGetSymbolAddress((void**)&d_xh,  g_xh);

    const int gemm_smem = 2 * GS_BUF * 16;

    convert_x_kernel<<<1024, 256>>>((const float4*)X, (uint4*)d_ah);
    transpose_w_kernel<<<dim3(24, 8), 256>>>(Wqkv,  d_wqt, 768);
    transpose_w_kernel<<<dim3(8, 8),  256>>>(Wproj, d_wpt, 256);

    cudaFuncSetAttribute(gemm_f16_kernel<false>,
                         cudaFuncAttributeMaxDynamicSharedMemorySize, gemm_smem);
    gemm_f16_kernel<false><<<dim3(6, 64), 256, gemm_smem>>>(
        (const uint4*)d_ah, (const uint4*)d_wqt, nullptr, nullptr);

    cudaFuncSetAttribute(attn_mma_kernel,
                         cudaFuncAttributeMaxDynamicSharedMemorySize, ATT_SMEM);
    attn_mma_kernel<<<BB * 32, 256, ATT_SMEM>>>(rp, rel_len, btab);

    cudaFuncSetAttribute(gemm_f16_kernel<true>,
                         cudaFuncAttributeMaxDynamicSharedMemorySize, gemm_smem);
    gemm_f16_kernel<true><<<dim3(2, 64), 256, gemm_smem>>>(
        (const uint4*)d_xh, (const uint4*)d_wpt, out, bproj);
}

// round 8
// speedup vs baseline: 1.4603x; 1.0821x over previous
#include <cuda_runtime.h>
#include <cuda_fp16.h>
#include <cstdint>

#define BB 8
#define NN 1024
#define CC 256
#define HH 8
#define HD 32
#define TABLE 10

// Scratch (allocation-free rule: __device__ globals)
__device__ __half g_ah [BB*NN*CC];      // X in fp16, row-major [8192][256]
__device__ __half g_wqt[3*CC*CC];       // W_qkv^T fp16 [768][256]
__device__ __half g_wpt[CC*CC];         // W_proj^T fp16 [256][256]
__device__ __half g_qh [BB*HH*NN*HD];   // q * scale * log2e, fp16
__device__ __half g_kh [BB*HH*NN*HD];
__device__ __half g_vh [BB*HH*NN*HD];
__device__ __half g_xh [BB*NN*CC];      // attention output fp16 [8192][256]

// ---------------------------------------------------------------------------
// helpers
// ---------------------------------------------------------------------------
__device__ __forceinline__ void mma_f16(float* c, const uint32_t* a, const uint32_t* b) {
    asm volatile(
        "mma.sync.aligned.m16n8k16.row.col.f32.f16.f16.f32 "
        "{%0,%1,%2,%3},{%4,%5,%6,%7},{%8,%9},{%0,%1,%2,%3};\n"
        : "+f"(c[0]), "+f"(c[1]), "+f"(c[2]), "+f"(c[3])
        : "r"(a[0]), "r"(a[1]), "r"(a[2]), "r"(a[3]), "r"(b[0]), "r"(b[1]));
}
__device__ __forceinline__ void ldsm4(uint32_t* r, uint32_t addr) {
    asm volatile("ldmatrix.sync.aligned.m8n8.x4.shared.b16 {%0,%1,%2,%3},[%4];"
                 : "=r"(r[0]), "=r"(r[1]), "=r"(r[2]), "=r"(r[3]) : "r"(addr));
}
__device__ __forceinline__ void ldsm4t(uint32_t* r, uint32_t addr) {
    asm volatile("ldmatrix.sync.aligned.m8n8.x4.trans.shared.b16 {%0,%1,%2,%3},[%4];"
                 : "=r"(r[0]), "=r"(r[1]), "=r"(r[2]), "=r"(r[3]) : "r"(addr));
}
__device__ __forceinline__ uint32_t smem_u32(const void* p) {
    uint32_t a;
    asm("{ .reg .u64 t; cvta.to.shared.u64 t, %1; cvt.u32.u64 %0, t; }" : "=r"(a) : "l"(p));
    return a;
}
__device__ __forceinline__ void cp16(uint32_t dst, const void* src) {
    asm volatile("cp.async.ca.shared.global [%0],[%1],16;" :: "r"(dst), "l"(src));
}
__device__ __forceinline__ void cp_commit() { asm volatile("cp.async.commit_group;"); }
__device__ __forceinline__ void cp_wait0()  { asm volatile("cp.async.wait_group 0;"); }
__device__ __forceinline__ void cp_wait1()  { asm volatile("cp.async.wait_group 1;"); }
__device__ __forceinline__ uint32_t ex2h2(uint32_t x) {
    uint32_t r;
    asm("ex2.approx.f16x2 %0, %1;" : "=r"(r) : "r"(x));
    return r;
}
__device__ __forceinline__ uint32_t pack2(float lo, float hi) {
    __half2 h = __floats2half2_rn(lo, hi);
    return *(uint32_t*)&h;
}

// ---------------------------------------------------------------------------
// Conversions
// ---------------------------------------------------------------------------
__global__ void __launch_bounds__(256) convert_x_kernel(const float4* __restrict__ X,
                                                        uint4* __restrict__ out)
{
    int idx = blockIdx.x * 256 + threadIdx.x;
    float4 a = X[idx * 2], b = X[idx * 2 + 1];
    __half2 h0 = __floats2half2_rn(a.x, a.y);
    __half2 h1 = __floats2half2_rn(a.z, a.w);
    __half2 h2 = __floats2half2_rn(b.x, b.y);
    __half2 h3 = __floats2half2_rn(b.z, b.w);
    out[idx] = make_uint4(*(uint32_t*)&h0, *(uint32_t*)&h1,
                          *(uint32_t*)&h2, *(uint32_t*)&h3);
}

__global__ void __launch_bounds__(256) transpose_w_kernel(const float* __restrict__ W,
                                                          __half* __restrict__ Wt, int N)
{
    __shared__ float tile[32][33];
    int n0 = blockIdx.x * 32, k0 = blockIdx.y * 32;
    int tx = threadIdx.x & 31, ty = threadIdx.x >> 5;
    #pragma unroll
    for (int i = 0; i < 4; i++)
        tile[ty + i * 8][tx] = W[(k0 + ty + i * 8) * N + n0 + tx];
    __syncthreads();
    #pragma unroll
    for (int i = 0; i < 4; i++)
        Wt[(n0 + ty + i * 8) * 256 + k0 + tx] = __float2half_rn(tile[tx][ty + i * 8]);
}

// ---------------------------------------------------------------------------
// fp16 tensor-core GEMM: C[M,N] = A[M,256] @ Wt[N,256]^T  (unchanged from R6)
// ---------------------------------------------------------------------------
#define GS_ROW 9
#define GS_TILE (128 * GS_ROW)
#define GS_BUF  (2 * GS_TILE)

template<bool PROJ>
__global__ void __launch_bounds__(256) gemm_f16_kernel(
    const uint4* __restrict__ A4, const uint4* __restrict__ B4,
    float* __restrict__ outp, const float* __restrict__ bias)
{
    extern __shared__ uint4 smem4[];
    const int tid  = threadIdx.x;
    const int warp = tid >> 5, lane = tid & 31;
    const int g = lane >> 2, t = lane & 3;
    const int m0 = blockIdx.y * 128, n0 = blockIdx.x * 128;
    const int wm = warp >> 2, wn = warp & 3;
    const uint32_t sb = smem_u32(smem4);
    const int arow = lane & 15, chi = lane >> 4;

    float acc[4][4][4];
    #pragma unroll
    for (int mt = 0; mt < 4; mt++)
        #pragma unroll
        for (int nt = 0; nt < 4; nt++)
            #pragma unroll
            for (int r = 0; r < 4; r++) acc[mt][nt][r] = 0.f;

    auto load_chunk = [&](int c, int buf) {
        #pragma unroll
        for (int i = 0; i < 4; i++) {
            int idx = i * 256 + tid;
            int row = idx >> 3, cc = idx & 7;
            uint32_t da = sb + (uint32_t)(buf * GS_BUF + row * GS_ROW + cc) * 16;
            cp16(da, &A4[(long)(m0 + row) * 32 + c * 8 + cc]);
            uint32_t db = sb + (uint32_t)(buf * GS_BUF + GS_TILE + row * GS_ROW + cc) * 16;
            cp16(db, &B4[(long)(n0 + row) * 32 + c * 8 + cc]);
        }
        cp_commit();
    };

    load_chunk(0, 0);

    for (int c = 0; c < 4; c++) {
        cp_wait0();
        __syncthreads();
        if (c < 3) load_chunk(c + 1, (c + 1) & 1);
        const int bo = (c & 1) * GS_BUF;

        #pragma unroll
        for (int ks = 0; ks < 4; ks++) {
            uint32_t af[4][4];
            #pragma unroll
            for (int mt = 0; mt < 4; mt++)
                ldsm4(af[mt], sb + (uint32_t)(bo + (wm * 64 + mt * 16 + arow) * GS_ROW
                                              + ks * 2 + chi) * 16);
            uint32_t bf[2][4];
            #pragma unroll
            for (int np = 0; np < 2; np++)
                ldsm4(bf[np], sb + (uint32_t)(bo + GS_TILE
                                              + (wn * 32 + np * 16 + arow) * GS_ROW
                                              + ks * 2 + chi) * 16);
            #pragma unroll
            for (int mt = 0; mt < 4; mt++)
                #pragma unroll
                for (int nt = 0; nt < 4; nt++) {
                    uint32_t bb[2] = { bf[nt >> 1][nt & 1], bf[nt >> 1][(nt & 1) + 2] };
                    mma_f16(acc[mt][nt], af[mt], bb);
                }
        }
        __syncthreads();
    }

    if (PROJ) {
        #pragma unroll
        for (int mt = 0; mt < 4; mt++) {
            int m = m0 + wm * 64 + mt * 16 + g;
            #pragma unroll
            for (int nt = 0; nt < 4; nt++) {
                int col = n0 + wn * 32 + nt * 8 + 2 * t;
                float b0 = bias[col], b1 = bias[col + 1];
                *(float2*)&outp[(long)m * 256 + col] =
                    make_float2(acc[mt][nt][0] + b0, acc[mt][nt][1] + b1);
                *(float2*)&outp[(long)(m + 8) * 256 + col] =
                    make_float2(acc[mt][nt][2] + b0, acc[mt][nt][3] + b1);
            }
        }
    } else {
        // scale = 32^-0.5 * log2(e), folded into q for the ex2-domain softmax
        const float scale = 0.25503483f;
        #pragma unroll
        for (int mt = 0; mt < 4; mt++) {
            int m = m0 + wm * 64 + mt * 16 + g;
            int bb = m >> 10, nn = m & 1023;
            #pragma unroll
            for (int nt = 0; nt < 4; nt++) {
                int col = n0 + wn * 32 + nt * 8 + 2 * t;
                int sel = col >> 8, hh = (col >> 5) & 7, dd = col & 31;
                float c0 = acc[mt][nt][0], c1 = acc[mt][nt][1];
                float c2 = acc[mt][nt][2], c3 = acc[mt][nt][3];
                if (sel == 0) { c0 *= scale; c1 *= scale; c2 *= scale; c3 *= scale; }
                __half* dst = (sel == 0) ? g_qh : (sel == 1) ? g_kh : g_vh;
                long base = (((long)bb * HH + hh) * NN + nn) * HD + dd;
                *(__half2*)&dst[base]           = __floats2half2_rn(c0, c1);
                *(__half2*)&dst[base + 8 * HD]  = __floats2half2_rn(c2, c3);
            }
        }
    }
}

// ---------------------------------------------------------------------------
// Fused flash attention v3: fixed-shift softmax (no running max).
//   raw K/V layout + ldmatrix(.trans), cp.async double buffer,
//   p = ex2(l2 - SHIFT) with SHIFT folded into the MMA accumulator init,
//   ones-column row sums, no O rescaling.
// Block = (batch, 32 query rows), 8 warps = 8 heads.
// ---------------------------------------------------------------------------
#define KROWB   80                      // bytes per K/V row (32 halves + pad)
#define HEADB   (32 * KROWB)            // 2560 B per head tile
#define VOFF    (8 * HEADB)             // 20480
#define RPOFF   (2 * 8 * HEADB)         // 40960
#define RPROWB  144                     // 32 ints + pad, 16B aligned
#define BUFB    (RPOFF + 32 * RPROWB)   // 45568 per stage
#define ATT_SMEM (2 * BUFB)             // 91136
#define SOFT_SHIFT 4.0f                 // fixed log2-domain shift

__global__ void __launch_bounds__(256, 2) attn_mma_kernel(
    const int* __restrict__ rp, const int* __restrict__ rel_len,
    const float* __restrict__ bias_table)
{
    extern __shared__ char smc[];
    const uint32_t sb = smem_u32(smc);

    const int tid  = threadIdx.x;
    const int h    = tid >> 5;
    const int lane = tid & 31;
    const int g    = lane >> 2;
    const int t    = lane & 3;
    const int b    = blockIdx.x >> 5;
    const int row0 = (blockIdx.x & 31) * 32;

    // per-head masked bias table (log2 domain), lane registers for shfl lookup
    const int mask_len = (int)(__int2float_rn(rel_len[b]) * 0.5f);
    float bt2 = 0.f;
    if (lane < TABLE)
        bt2 = bias_table[lane * HH + h] * 1.4426950408889634f
            + ((lane > mask_len) ? -144.2695040888963f : 0.f);

    // one-time: fill V pad columns (d=32..39) with fp16 ones, both buffers
    {
        const uint4 ones = make_uint4(0x3C003C00u, 0x3C003C00u, 0x3C003C00u, 0x3C003C00u);
        #pragma unroll
        for (int i = 0; i < 2; i++) {
            int row = tid + i * 256;
            int buf = row >> 8, rem = row & 255;
            *(uint4*)(smc + buf * BUFB + VOFF + rem * KROWB + 64) = ones;
        }
    }

    // Q fragments (scale*log2e pre-folded)
    uint32_t qa[2][2][4];
    {
        const uint32_t* qw = (const uint32_t*)g_qh;
        long rbase = ((long)(b * HH) + h) * NN + row0;
        #pragma unroll
        for (int mt = 0; mt < 2; mt++) {
            long rA = (rbase + mt * 16 + g) * 16;
            long rB = rA + 8 * 16;
            #pragma unroll
            for (int ks = 0; ks < 2; ks++) {
                int w = ks * 8 + t;
                qa[mt][ks][0] = qw[rA + w];
                qa[mt][ks][1] = qw[rB + w];
                qa[mt][ks][2] = qw[rA + w + 4];
                qa[mt][ks][3] = qw[rB + w + 4];
            }
        }
    }

    float o[2][5][4];                       // nt=4 is the ones column (row sums)
    #pragma unroll
    for (int mt = 0; mt < 2; mt++)
        #pragma unroll
        for (int nt = 0; nt < 5; nt++)
            #pragma unroll
            for (int r = 0; r < 4; r++) o[mt][nt][r] = 0.f;

    const __half* gk = g_kh;
    const __half* gv = g_vh;

    auto prefetch = [&](int j, int buf) {
        uint32_t base = sb + buf * BUFB;
        long kvbase = (((long)b * HH) * NN + j * 32) * HD;
        #pragma unroll
        for (int i = 0; i < 4; i++) {
            int idx = i * 256 + tid;
            int ch = idx & 3, key = (idx >> 2) & 31, h2 = idx >> 7;
            long src = kvbase + (long)h2 * (NN * HD) + key * HD + ch * 8;
            uint32_t d = base + h2 * HEADB + key * KROWB + ch * 16;
            cp16(d, gk + src);
            cp16(d + VOFF, gv + src);
        }
        {
            int r = tid >> 3, ch = tid & 7;
            cp16(base + RPOFF + r * RPROWB + ch * 16,
                 rp + ((long)b * NN + row0 + r) * NN + j * 32 + ch * 4);
        }
        cp_commit();
    };

    prefetch(0, 0);

    const int ln8 = lane & 7, l8 = lane >> 3;

    for (int j = 0; j < 32; j++) {
        const int buf = j & 1;
        __syncthreads();                       // everyone done reading buf^1
        if (j + 1 < 32) { prefetch(j + 1, buf ^ 1); cp_wait1(); }
        else            { cp_wait0(); }
        __syncthreads();

        const uint32_t bo  = sb + buf * BUFB;
        const uint32_t kha = bo + h * HEADB;
        const uint32_t vha = kha + VOFF;
        const char*    rpb = smc + buf * BUFB + RPOFF;

        // ---- S = Q @ K^T, accumulator pre-loaded with -SHIFT ----
        float c[2][4][4];
        #pragma unroll
        for (int mt = 0; mt < 2; mt++)
            #pragma unroll
            for (int nt = 0; nt < 4; nt++)
                #pragma unroll
                for (int r = 0; r < 4; r++) c[mt][nt][r] = -SOFT_SHIFT;
        {
            uint32_t kb[4][4];
            uint32_t ka = kha + (uint32_t)(ln8 * KROWB + l8 * 16);
            #pragma unroll
            for (int nt = 0; nt < 4; nt++)
                ldsm4(kb[nt], ka + nt * (8 * KROWB));
            #pragma unroll
            for (int nt = 0; nt < 4; nt++)
                #pragma unroll
                for (int ks = 0; ks < 2; ks++) {
                    uint32_t bf[2] = { kb[nt][2 * ks], kb[nt][2 * ks + 1] };
                    mma_f16(c[0][nt], qa[0][ks], bf);
                    mma_f16(c[1][nt], qa[1][ks], bf);
                }
        }

        // ---- V frags early (independent of softmax) ----
        uint32_t vb[5][4];
        {
            uint32_t va = vha + (uint32_t)(lane * KROWB);
            #pragma unroll
            for (int nt = 0; nt < 5; nt++)
                ldsm4t(vb[nt], va + nt * 16);
        }

        // ---- bias + fixed-shift softmax -> P A-frags ----
        uint32_t pa[2][2][4];
        #pragma unroll
        for (int mt = 0; mt < 2; mt++) {
            int rA = mt * 16 + g, rB = rA + 8;
            uint32_t hA[4], hB[4];
            #pragma unroll
            for (int nt = 0; nt < 4; nt++) {
                int colb = nt * 8 + 2 * t;
                int2 ra = *(const int2*)(rpb + rA * RPROWB + colb * 4);
                int2 rb = *(const int2*)(rpb + rB * RPROWB + colb * 4);
                float c0 = c[mt][nt][0] + __shfl_sync(0xffffffffu, bt2, ra.x);
                float c1 = c[mt][nt][1] + __shfl_sync(0xffffffffu, bt2, ra.y);
                float c2 = c[mt][nt][2] + __shfl_sync(0xffffffffu, bt2, rb.x);
                float c3 = c[mt][nt][3] + __shfl_sync(0xffffffffu, bt2, rb.y);
                hA[nt] = ex2h2(pack2(c0, c1));
                hB[nt] = ex2h2(pack2(c2, c3));
            }
            #pragma unroll
            for (int ks = 0; ks < 2; ks++) {
                pa[mt][ks][0] = hA[2 * ks];
                pa[mt][ks][1] = hB[2 * ks];
                pa[mt][ks][2] = hA[2 * ks + 1];
                pa[mt][ks][3] = hB[2 * ks + 1];
            }
        }

        // ---- O += P @ [V | 1] ----
        #pragma unroll
        for (int ks = 0; ks < 2; ks++)
            #pragma unroll
            for (int nt = 0; nt < 5; nt++) {
                uint32_t bf[2] = { vb[nt][2 * ks], vb[nt][2 * ks + 1] };
                mma_f16(o[0][nt], pa[0][ks], bf);
                mma_f16(o[1][nt], pa[1][ks], bf);
            }
    }

    // ---- epilogue: normalize by ones-column sums, store fp16 to g_xh ----
    #pragma unroll
    for (int mt = 0; mt < 2; mt++) {
        float i0 = 1.f / o[mt][4][0];
        float i1 = 1.f / o[mt][4][2];
        int rA = row0 + mt * 16 + g;
        #pragma unroll
        for (int nt = 0; nt < 4; nt++) {
            int col = h * HD + nt * 8 + 2 * t;
            *(__half2*)&g_xh[((long)b * NN + rA) * CC + col] =
                __floats2half2_rn(o[mt][nt][0] * i0, o[mt][nt][1] * i0);
            *(__half2*)&g_xh[((long)b * NN + rA + 8) * CC + col] =
                __floats2half2_rn(o[mt][nt][2] * i1, o[mt][nt][3] * i1);
        }
    }
}

// ---------------------------------------------------------------------------
extern "C" void kernel_launch(void* const* d_in, const int* in_sizes, int n_in,
                              void* d_out, int out_size)
{
    const float* X       = (const float*)d_in[0];
    const int*   rp      = (const int*)  d_in[1];
    const int*   rel_len = (const int*)  d_in[2];
    const float* Wqkv    = (const float*)d_in[3];
    const float* Wproj   = (const float*)d_in[4];
    const float* bproj   = (const float*)d_in[5];
    const float* btab    = (const float*)d_in[6];
    float* out = (float*)d_out;

    __half* d_ah;   cudaGetSymbolAddress((void**)&d_ah,  g_ah);
    __half* d_wqt;  cudaGetSymbolAddress((void**)&d_wqt, g_wqt);
    __half* d_wpt;  cudaGetSymbolAddress((void**)&d_wpt, g_wpt);
    __half* d_xh;   cudaGetSymbolAddress((void**)&d_xh,  g_xh);

    const int gemm_smem = 2 * GS_BUF * 16;

    convert_x_kernel<<<1024, 256>>>((const float4*)X, (uint4*)d_ah);
    transpose_w_kernel<<<dim3(24, 8), 256>>>(Wqkv,  d_wqt, 768);
    transpose_w_kernel<<<dim3(8, 8),  256>>>(Wproj, d_wpt, 256);

    cudaFuncSetAttribute(gemm_f16_kernel<false>,
                         cudaFuncAttributeMaxDynamicSharedMemorySize, gemm_smem);
    gemm_f16_kernel<false><<<dim3(6, 64), 256, gemm_smem>>>(
        (const uint4*)d_ah, (const uint4*)d_wqt, nullptr, nullptr);

    cudaFuncSetAttribute(attn_mma_kernel,
                         cudaFuncAttributeMaxDynamicSharedMemorySize, ATT_SMEM);
    attn_mma_kernel<<<BB * 32, 256, ATT_SMEM>>>(rp, rel_len, btab);

    cudaFuncSetAttribute(gemm_f16_kernel<true>,
                         cudaFuncAttributeMaxDynamicSharedMemorySize, gemm_smem);
    gemm_f16_kernel<true><<<dim3(2, 64), 256, gemm_smem>>>(
        (const uint4*)d_xh, (const uint4*)d_wpt, out, bproj);
}

// round 9
// speedup vs baseline: 1.4967x; 1.0249x over previous
#include <cuda_runtime.h>
#include <cuda_fp16.h>
#include <cstdint>

#define BB 8
#define NN 1024
#define CC 256
#define HH 8
#define HD 32
#define TABLE 10

// Scratch (allocation-free rule: __device__ globals)
__device__ __half   g_ah [BB*NN*CC];      // X in fp16, row-major [8192][256]
__device__ __half   g_wqt[3*CC*CC];       // W_qkv^T fp16 [768][256]
__device__ __half   g_wpt[CC*CC];         // W_proj^T fp16 [256][256]
__device__ __half   g_qh [BB*HH*NN*HD];   // q * scale * log2e, fp16
__device__ __half   g_kh [BB*HH*NN*HD];
__device__ __half   g_vh [BB*HH*NN*HD];
__device__ __half   g_xh [BB*NN*CC];      // attention output fp16 [8192][256]
__device__ uint8_t  g_rpn[BB*NN*NN/2];    // relation_position nibble-packed

// ---------------------------------------------------------------------------
// helpers
// ---------------------------------------------------------------------------
__device__ __forceinline__ void mma_f16(float* c, const uint32_t* a, const uint32_t* b) {
    asm volatile(
        "mma.sync.aligned.m16n8k16.row.col.f32.f16.f16.f32 "
        "{%0,%1,%2,%3},{%4,%5,%6,%7},{%8,%9},{%0,%1,%2,%3};\n"
        : "+f"(c[0]), "+f"(c[1]), "+f"(c[2]), "+f"(c[3])
        : "r"(a[0]), "r"(a[1]), "r"(a[2]), "r"(a[3]), "r"(b[0]), "r"(b[1]));
}
__device__ __forceinline__ void ldsm4(uint32_t* r, uint32_t addr) {
    asm volatile("ldmatrix.sync.aligned.m8n8.x4.shared.b16 {%0,%1,%2,%3},[%4];"
                 : "=r"(r[0]), "=r"(r[1]), "=r"(r[2]), "=r"(r[3]) : "r"(addr));
}
__device__ __forceinline__ void ldsm4t(uint32_t* r, uint32_t addr) {
    asm volatile("ldmatrix.sync.aligned.m8n8.x4.trans.shared.b16 {%0,%1,%2,%3},[%4];"
                 : "=r"(r[0]), "=r"(r[1]), "=r"(r[2]), "=r"(r[3]) : "r"(addr));
}
__device__ __forceinline__ uint32_t smem_u32(const void* p) {
    uint32_t a;
    asm("{ .reg .u64 t; cvta.to.shared.u64 t, %1; cvt.u32.u64 %0, t; }" : "=r"(a) : "l"(p));
    return a;
}
__device__ __forceinline__ void cp16(uint32_t dst, const void* src) {
    asm volatile("cp.async.ca.shared.global [%0],[%1],16;" :: "r"(dst), "l"(src));
}
__device__ __forceinline__ void cp_commit() { asm volatile("cp.async.commit_group;"); }
__device__ __forceinline__ void cp_wait0()  { asm volatile("cp.async.wait_group 0;"); }
__device__ __forceinline__ void cp_wait1()  { asm volatile("cp.async.wait_group 1;"); }
__device__ __forceinline__ uint32_t ex2h2(uint32_t x) {
    uint32_t r;
    asm("ex2.approx.f16x2 %0, %1;" : "=r"(r) : "r"(x));
    return r;
}
__device__ __forceinline__ uint32_t hadd2u(uint32_t a, uint32_t b) {
    __half2 r = __hadd2(*(__half2*)&a, *(__half2*)&b);
    return *(uint32_t*)&r;
}
__device__ __forceinline__ uint32_t pack2(float lo, float hi) {
    __half2 h = __floats2half2_rn(lo, hi);
    return *(uint32_t*)&h;
}

// ---------------------------------------------------------------------------
// Conversions
// ---------------------------------------------------------------------------
__global__ void __launch_bounds__(256) convert_x_kernel(const float4* __restrict__ X,
                                                        uint4* __restrict__ out)
{
    int idx = blockIdx.x * 256 + threadIdx.x;
    float4 a = X[idx * 2], b = X[idx * 2 + 1];
    __half2 h0 = __floats2half2_rn(a.x, a.y);
    __half2 h1 = __floats2half2_rn(a.z, a.w);
    __half2 h2 = __floats2half2_rn(b.x, b.y);
    __half2 h3 = __floats2half2_rn(b.z, b.w);
    out[idx] = make_uint4(*(uint32_t*)&h0, *(uint32_t*)&h1,
                          *(uint32_t*)&h2, *(uint32_t*)&h3);
}

// rp int32 -> nibble pack (values 0..9): 8 ints -> 1 uint32
__global__ void __launch_bounds__(256) rp_nibble_kernel(const int4* __restrict__ rp,
                                                        uint32_t* __restrict__ out)
{
    int idx = blockIdx.x * 256 + threadIdx.x;   // 1,048,576 total
    int4 a = rp[idx * 2], b = rp[idx * 2 + 1];
    out[idx] = (uint32_t)a.x | ((uint32_t)a.y << 4)  | ((uint32_t)a.z << 8)
             | ((uint32_t)a.w << 12) | ((uint32_t)b.x << 16) | ((uint32_t)b.y << 20)
             | ((uint32_t)b.z << 24) | ((uint32_t)b.w << 28);
}

__global__ void __launch_bounds__(256) transpose_w_kernel(const float* __restrict__ W,
                                                          __half* __restrict__ Wt, int N)
{
    __shared__ float tile[32][33];
    int n0 = blockIdx.x * 32, k0 = blockIdx.y * 32;
    int tx = threadIdx.x & 31, ty = threadIdx.x >> 5;
    #pragma unroll
    for (int i = 0; i < 4; i++)
        tile[ty + i * 8][tx] = W[(k0 + ty + i * 8) * N + n0 + tx];
    __syncthreads();
    #pragma unroll
    for (int i = 0; i < 4; i++)
        Wt[(n0 + ty + i * 8) * 256 + k0 + tx] = __float2half_rn(tile[tx][ty + i * 8]);
}

// ---------------------------------------------------------------------------
// fp16 tensor-core GEMM: C[M,N] = A[M,256] @ Wt[N,256]^T  (unchanged)
// ---------------------------------------------------------------------------
#define GS_ROW 9
#define GS_TILE (128 * GS_ROW)
#define GS_BUF  (2 * GS_TILE)

template<bool PROJ>
__global__ void __launch_bounds__(256) gemm_f16_kernel(
    const uint4* __restrict__ A4, const uint4* __restrict__ B4,
    float* __restrict__ outp, const float* __restrict__ bias)
{
    extern __shared__ uint4 smem4[];
    const int tid  = threadIdx.x;
    const int warp = tid >> 5, lane = tid & 31;
    const int g = lane >> 2, t = lane & 3;
    const int m0 = blockIdx.y * 128, n0 = blockIdx.x * 128;
    const int wm = warp >> 2, wn = warp & 3;
    const uint32_t sb = smem_u32(smem4);
    const int arow = lane & 15, chi = lane >> 4;

    float acc[4][4][4];
    #pragma unroll
    for (int mt = 0; mt < 4; mt++)
        #pragma unroll
        for (int nt = 0; nt < 4; nt++)
            #pragma unroll
            for (int r = 0; r < 4; r++) acc[mt][nt][r] = 0.f;

    auto load_chunk = [&](int c, int buf) {
        #pragma unroll
        for (int i = 0; i < 4; i++) {
            int idx = i * 256 + tid;
            int row = idx >> 3, cc = idx & 7;
            uint32_t da = sb + (uint32_t)(buf * GS_BUF + row * GS_ROW + cc) * 16;
            cp16(da, &A4[(long)(m0 + row) * 32 + c * 8 + cc]);
            uint32_t db = sb + (uint32_t)(buf * GS_BUF + GS_TILE + row * GS_ROW + cc) * 16;
            cp16(db, &B4[(long)(n0 + row) * 32 + c * 8 + cc]);
        }
        cp_commit();
    };

    load_chunk(0, 0);

    for (int c = 0; c < 4; c++) {
        cp_wait0();
        __syncthreads();
        if (c < 3) load_chunk(c + 1, (c + 1) & 1);
        const int bo = (c & 1) * GS_BUF;

        #pragma unroll
        for (int ks = 0; ks < 4; ks++) {
            uint32_t af[4][4];
            #pragma unroll
            for (int mt = 0; mt < 4; mt++)
                ldsm4(af[mt], sb + (uint32_t)(bo + (wm * 64 + mt * 16 + arow) * GS_ROW
                                              + ks * 2 + chi) * 16);
            uint32_t bf[2][4];
            #pragma unroll
            for (int np = 0; np < 2; np++)
                ldsm4(bf[np], sb + (uint32_t)(bo + GS_TILE
                                              + (wn * 32 + np * 16 + arow) * GS_ROW
                                              + ks * 2 + chi) * 16);
            #pragma unroll
            for (int mt = 0; mt < 4; mt++)
                #pragma unroll
                for (int nt = 0; nt < 4; nt++) {
                    uint32_t bb[2] = { bf[nt >> 1][nt & 1], bf[nt >> 1][(nt & 1) + 2] };
                    mma_f16(acc[mt][nt], af[mt], bb);
                }
        }
        __syncthreads();
    }

    if (PROJ) {
        #pragma unroll
        for (int mt = 0; mt < 4; mt++) {
            int m = m0 + wm * 64 + mt * 16 + g;
            #pragma unroll
            for (int nt = 0; nt < 4; nt++) {
                int col = n0 + wn * 32 + nt * 8 + 2 * t;
                float b0 = bias[col], b1 = bias[col + 1];
                *(float2*)&outp[(long)m * 256 + col] =
                    make_float2(acc[mt][nt][0] + b0, acc[mt][nt][1] + b1);
                *(float2*)&outp[(long)(m + 8) * 256 + col] =
                    make_float2(acc[mt][nt][2] + b0, acc[mt][nt][3] + b1);
            }
        }
    } else {
        const float scale = 0.25503483f;   // 32^-0.5 * log2(e)
        #pragma unroll
        for (int mt = 0; mt < 4; mt++) {
            int m = m0 + wm * 64 + mt * 16 + g;
            int bb = m >> 10, nn = m & 1023;
            #pragma unroll
            for (int nt = 0; nt < 4; nt++) {
                int col = n0 + wn * 32 + nt * 8 + 2 * t;
                int sel = col >> 8, hh = (col >> 5) & 7, dd = col & 31;
                float c0 = acc[mt][nt][0], c1 = acc[mt][nt][1];
                float c2 = acc[mt][nt][2], c3 = acc[mt][nt][3];
                if (sel == 0) { c0 *= scale; c1 *= scale; c2 *= scale; c3 *= scale; }
                __half* dst = (sel == 0) ? g_qh : (sel == 1) ? g_kh : g_vh;
                long base = (((long)bb * HH + hh) * NN + nn) * HD + dd;
                *(__half2*)&dst[base]           = __floats2half2_rn(c0, c1);
                *(__half2*)&dst[base + 8 * HD]  = __floats2half2_rn(c2, c3);
            }
        }
    }
}

// ---------------------------------------------------------------------------
// Fused flash attention v4: warp-autonomous, ZERO block barriers.
// Each warp (head) owns a private smem region + private cp.async pipeline:
//   [stage0: K|V|rpn][stage1: K|V|rpn][bias pair table 160*half2]
// Fixed-shift ex2 softmax; bias via nibble-pair table lookup + HADD2.
// ---------------------------------------------------------------------------
#define AKROWB 80                       // bytes per K/V row (32 halves + pad)
#define AKTILE (32 * AKROWB)            // 2560
#define ASTAGE (2 * AKTILE + 512)       // K + V + rpn = 5632
#define AWARP  (2 * ASTAGE + 640)       // 2 stages + table = 11904
#define ATT_SMEM (8 * AWARP)            // 95232
#define SOFT_SHIFT 4.0f

__global__ void __launch_bounds__(256, 2) attn_mma_kernel(
    const int* __restrict__ rel_len, const float* __restrict__ bias_table)
{
    extern __shared__ char smc[];

    const int tid  = threadIdx.x;
    const int h    = tid >> 5;
    const int lane = tid & 31;
    const int g    = lane >> 2;
    const int t    = lane & 3;
    const int b    = blockIdx.x >> 5;
    const int row0 = (blockIdx.x & 31) * 32;

    char* smw = smc + h * AWARP;                    // this warp's private region
    const uint32_t sbw = smem_u32(smw);
    uint32_t* tblp = (uint32_t*)(smw + 2 * ASTAGE); // 160-entry half2 pair table

    // ---- per-head masked bias table (log2 domain) -> pair table in smem ----
    {
        const int mask_len = (int)(__int2float_rn(rel_len[b]) * 0.5f);
        float btl2 = 0.f;
        if (lane < TABLE)
            btl2 = bias_table[lane * HH + h] * 1.4426950408889634f
                 + ((lane > mask_len) ? -144.2695040888963f : 0.f);
        #pragma unroll
        for (int i = lane; i < 160; i += 32) {
            float lo = __shfl_sync(0xffffffffu, btl2, i & 15);
            float hi = __shfl_sync(0xffffffffu, btl2, i >> 4);
            tblp[i] = pack2(lo, hi);
        }
    }

    // ---- V pad columns (d=32..39) = fp16 ones, both stages (warp-private) ----
    {
        const uint4 ones = make_uint4(0x3C003C00u, 0x3C003C00u, 0x3C003C00u, 0x3C003C00u);
        #pragma unroll
        for (int i = 0; i < 2; i++) {
            int row = lane + i * 32;       // 64: [stage][row]
            int stg = row >> 5, rem = row & 31;
            *(uint4*)(smw + stg * ASTAGE + AKTILE + rem * AKROWB + 64) = ones;
        }
    }

    // ---- Q fragments (scale*log2e pre-folded) ----
    uint32_t qa[2][2][4];
    {
        const uint32_t* qw = (const uint32_t*)g_qh;
        long rbase = ((long)(b * HH) + h) * NN + row0;
        #pragma unroll
        for (int mt = 0; mt < 2; mt++) {
            long rA = (rbase + mt * 16 + g) * 16;
            long rB = rA + 8 * 16;
            #pragma unroll
            for (int ks = 0; ks < 2; ks++) {
                int w = ks * 8 + t;
                qa[mt][ks][0] = qw[rA + w];
                qa[mt][ks][1] = qw[rB + w];
                qa[mt][ks][2] = qw[rA + w + 4];
                qa[mt][ks][3] = qw[rB + w + 4];
            }
        }
    }

    float o[2][5][4];                       // nt=4 is the ones column (row sums)
    #pragma unroll
    for (int mt = 0; mt < 2; mt++)
        #pragma unroll
        for (int nt = 0; nt < 5; nt++)
            #pragma unroll
            for (int r = 0; r < 4; r++) o[mt][nt][r] = 0.f;

    const __half*   gk   = g_kh;
    const __half*   gv   = g_vh;
    const uint8_t*  grpn = g_rpn;
    const long kvhead  = ((long)(b * HH) + h) * NN * HD;
    const long rpnrow  = ((long)b * NN + row0 + lane) * (NN / 2);

    // warp-private prefetch of tile j into stage stg (9 cp16 per lane)
    auto prefetch = [&](int j, int stg) {
        uint32_t base = sbw + stg * ASTAGE;
        long src = kvhead + (long)(j * 32) * HD;
        #pragma unroll
        for (int i = 0; i < 4; i++) {
            int idx = i * 32 + lane;           // 128: row = idx>>2, ch = idx&3
            int row = idx >> 2, ch = idx & 3;
            uint32_t d = base + row * AKROWB + ch * 16;
            cp16(d, gk + src + row * HD + ch * 8);
            cp16(d + AKTILE, gv + src + row * HD + ch * 8);
        }
        cp16(base + 2 * AKTILE + lane * 16, grpn + rpnrow + j * 16);
        cp_commit();
    };

    prefetch(0, 0);

    const int ln8 = lane & 7, l8 = lane >> 3;

    for (int j = 0; j < 32; j++) {
        const int stg = j & 1;
        if (j + 1 < 32) { prefetch(j + 1, stg ^ 1); cp_wait1(); }
        else            { cp_wait0(); }

        const uint32_t kbase = sbw + stg * ASTAGE;
        const uint32_t vbase = kbase + AKTILE;
        const uint8_t* rpn_s = (const uint8_t*)(smw + stg * ASTAGE + 2 * AKTILE);

        // ---- S = Q @ K^T, accumulator pre-loaded with -SHIFT ----
        float c[2][4][4];
        #pragma unroll
        for (int mt = 0; mt < 2; mt++)
            #pragma unroll
            for (int nt = 0; nt < 4; nt++)
                #pragma unroll
                for (int r = 0; r < 4; r++) c[mt][nt][r] = -SOFT_SHIFT;
        {
            uint32_t kb[4][4];
            uint32_t ka = kbase + (uint32_t)(ln8 * AKROWB + l8 * 16);
            #pragma unroll
            for (int nt = 0; nt < 4; nt++)
                ldsm4(kb[nt], ka + nt * (8 * AKROWB));
            #pragma unroll
            for (int nt = 0; nt < 4; nt++)
                #pragma unroll
                for (int ks = 0; ks < 2; ks++) {
                    uint32_t bf[2] = { kb[nt][2 * ks], kb[nt][2 * ks + 1] };
                    mma_f16(c[0][nt], qa[0][ks], bf);
                    mma_f16(c[1][nt], qa[1][ks], bf);
                }
        }

        // ---- V frags early (independent of softmax) ----
        uint32_t vb[5][4];
        {
            uint32_t va = vbase + (uint32_t)(lane * AKROWB);
            #pragma unroll
            for (int nt = 0; nt < 5; nt++)
                ldsm4t(vb[nt], va + nt * 16);
        }

        // ---- bias via pair table + fixed-shift ex2 softmax -> P A-frags ----
        uint32_t pa[2][2][4];
        #pragma unroll
        for (int mt = 0; mt < 2; mt++) {
            int rA = mt * 16 + g, rB = rA + 8;
            uint32_t hA[4], hB[4];
            #pragma unroll
            for (int nt = 0; nt < 4; nt++) {
                uint32_t iA = rpn_s[rA * 16 + nt * 4 + t];
                uint32_t iB = rpn_s[rB * 16 + nt * 4 + t];
                hA[nt] = ex2h2(hadd2u(pack2(c[mt][nt][0], c[mt][nt][1]), tblp[iA]));
                hB[nt] = ex2h2(hadd2u(pack2(c[mt][nt][2], c[mt][nt][3]), tblp[iB]));
            }
            #pragma unroll
            for (int ks = 0; ks < 2; ks++) {
                pa[mt][ks][0] = hA[2 * ks];
                pa[mt][ks][1] = hB[2 * ks];
                pa[mt][ks][2] = hA[2 * ks + 1];
                pa[mt][ks][3] = hB[2 * ks + 1];
            }
        }

        // ---- O += P @ [V | 1] ----
        #pragma unroll
        for (int ks = 0; ks < 2; ks++)
            #pragma unroll
            for (int nt = 0; nt < 5; nt++) {
                uint32_t bf[2] = { vb[nt][2 * ks], vb[nt][2 * ks + 1] };
                mma_f16(o[0][nt], pa[0][ks], bf);
                mma_f16(o[1][nt], pa[1][ks], bf);
            }
    }

    // ---- epilogue: normalize by ones-column sums, store fp16 to g_xh ----
    #pragma unroll
    for (int mt = 0; mt < 2; mt++) {
        float i0 = 1.f / o[mt][4][0];
        float i1 = 1.f / o[mt][4][2];
        int rA = row0 + mt * 16 + g;
        #pragma unroll
        for (int nt = 0; nt < 4; nt++) {
            int col = h * HD + nt * 8 + 2 * t;
            *(__half2*)&g_xh[((long)b * NN + rA) * CC + col] =
                __floats2half2_rn(o[mt][nt][0] * i0, o[mt][nt][1] * i0);
            *(__half2*)&g_xh[((long)b * NN + rA + 8) * CC + col] =
                __floats2half2_rn(o[mt][nt][2] * i1, o[mt][nt][3] * i1);
        }
    }
}

// ---------------------------------------------------------------------------
extern "C" void kernel_launch(void* const* d_in, const int* in_sizes, int n_in,
                              void* d_out, int out_size)
{
    const float* X       = (const float*)d_in[0];
    const int*   rp      = (const int*)  d_in[1];
    const int*   rel_len = (const int*)  d_in[2];
    const float* Wqkv    = (const float*)d_in[3];
    const float* Wproj   = (const float*)d_in[4];
    const float* bproj   = (const float*)d_in[5];
    const float* btab    = (const float*)d_in[6];
    float* out = (float*)d_out;

    __half*  d_ah;   cudaGetSymbolAddress((void**)&d_ah,  g_ah);
    __half*  d_wqt;  cudaGetSymbolAddress((void**)&d_wqt, g_wqt);
    __half*  d_wpt;  cudaGetSymbolAddress((void**)&d_wpt, g_wpt);
    __half*  d_xh;   cudaGetSymbolAddress((void**)&d_xh,  g_xh);
    uint8_t* d_rpn;  cudaGetSymbolAddress((void**)&d_rpn, g_rpn);

    const int gemm_smem = 2 * GS_BUF * 16;

    convert_x_kernel<<<1024, 256>>>((const float4*)X, (uint4*)d_ah);
    rp_nibble_kernel<<<4096, 256>>>((const int4*)rp, (uint32_t*)d_rpn);
    transpose_w_kernel<<<dim3(24, 8), 256>>>(Wqkv,  d_wqt, 768);
    transpose_w_kernel<<<dim3(8, 8),  256>>>(Wproj, d_wpt, 256);

    cudaFuncSetAttribute(gemm_f16_kernel<false>,
                         cudaFuncAttributeMaxDynamicSharedMemorySize, gemm_smem);
    gemm_f16_kernel<false><<<dim3(6, 64), 256, gemm_smem>>>(
        (const uint4*)d_ah, (const uint4*)d_wqt, nullptr, nullptr);

    cudaFuncSetAttribute(attn_mma_kernel,
                         cudaFuncAttributeMaxDynamicSharedMemorySize, ATT_SMEM);
    attn_mma_kernel<<<BB * 32, 256, ATT_SMEM>>>(rel_len, btab);

    cudaFuncSetAttribute(gemm_f16_kernel<true>,
                         cudaFuncAttributeMaxDynamicSharedMemorySize, gemm_smem);
    gemm_f16_kernel<true><<<dim3(2, 64), 256, gemm_smem>>>(
        (const uint4*)d_xh, (const uint4*)d_wpt, out, bproj);
}

// round 10
// speedup vs baseline: 1.5603x; 1.0425x over previous
#include <cuda_runtime.h>
#include <cuda_fp16.h>
#include <cstdint>

#define BB 8
#define NN 1024
#define CC 256
#define HH 8
#define HD 32
#define TABLE 10

// Scratch (allocation-free rule: __device__ globals)
__device__ __half   g_ah [BB*NN*CC];      // X fp16 [8192][256]
__device__ __half   g_wq [3*CC*CC];       // W_qkv fp16 [256][768]  (raw layout)
__device__ __half   g_wp [CC*CC];         // W_proj fp16 [256][256] (raw layout)
__device__ __half   g_qh [BB*HH*NN*HD];   // q * scale * log2e, fp16
__device__ __half   g_kh [BB*HH*NN*HD];
__device__ __half   g_vh [BB*HH*NN*HD];
__device__ __half   g_xh [BB*NN*CC];      // attention output fp16 [8192][256]
__device__ uint8_t  g_rpn[BB*NN*NN/2];    // rp nibble-packed, bytes permuted t*4+nt

// ---------------------------------------------------------------------------
// helpers
// ---------------------------------------------------------------------------
__device__ __forceinline__ void mma_f16(float* c, const uint32_t* a, const uint32_t* b) {
    asm volatile(
        "mma.sync.aligned.m16n8k16.row.col.f32.f16.f16.f32 "
        "{%0,%1,%2,%3},{%4,%5,%6,%7},{%8,%9},{%0,%1,%2,%3};\n"
        : "+f"(c[0]), "+f"(c[1]), "+f"(c[2]), "+f"(c[3])
        : "r"(a[0]), "r"(a[1]), "r"(a[2]), "r"(a[3]), "r"(b[0]), "r"(b[1]));
}
__device__ __forceinline__ void ldsm4(uint32_t* r, uint32_t addr) {
    asm volatile("ldmatrix.sync.aligned.m8n8.x4.shared.b16 {%0,%1,%2,%3},[%4];"
                 : "=r"(r[0]), "=r"(r[1]), "=r"(r[2]), "=r"(r[3]) : "r"(addr));
}
__device__ __forceinline__ void ldsm4t(uint32_t* r, uint32_t addr) {
    asm volatile("ldmatrix.sync.aligned.m8n8.x4.trans.shared.b16 {%0,%1,%2,%3},[%4];"
                 : "=r"(r[0]), "=r"(r[1]), "=r"(r[2]), "=r"(r[3]) : "r"(addr));
}
__device__ __forceinline__ uint32_t smem_u32(const void* p) {
    uint32_t a;
    asm("{ .reg .u64 t; cvta.to.shared.u64 t, %1; cvt.u32.u64 %0, t; }" : "=r"(a) : "l"(p));
    return a;
}
__device__ __forceinline__ void cp16(uint32_t dst, const void* src) {
    asm volatile("cp.async.ca.shared.global [%0],[%1],16;" :: "r"(dst), "l"(src));
}
__device__ __forceinline__ void cp_commit() { asm volatile("cp.async.commit_group;"); }
__device__ __forceinline__ void cp_wait0()  { asm volatile("cp.async.wait_group 0;"); }
__device__ __forceinline__ void cp_wait1()  { asm volatile("cp.async.wait_group 1;"); }
__device__ __forceinline__ uint32_t ex2h2(uint32_t x) {
    uint32_t r;
    asm("ex2.approx.f16x2 %0, %1;" : "=r"(r) : "r"(x));
    return r;
}
__device__ __forceinline__ uint32_t hadd2u(uint32_t a, uint32_t b) {
    __half2 r = __hadd2(*(__half2*)&a, *(__half2*)&b);
    return *(uint32_t*)&r;
}
__device__ __forceinline__ uint32_t pack2(float lo, float hi) {
    __half2 h = __floats2half2_rn(lo, hi);
    return *(uint32_t*)&h;
}

// ---------------------------------------------------------------------------
// Fused prep: X->fp16, Wqkv->fp16, Wproj->fp16, rp nibble-pack (permuted).
// One item = 8 floats (converts) or one 32-key rp group -> 16 bytes.
// ---------------------------------------------------------------------------
#define PREP_X  262144                   // 2,097,152 floats / 8
#define PREP_WQ (PREP_X + 24576)         // 196,608 / 8
#define PREP_WP (PREP_WQ + 8192)         // 65,536 / 8
#define PREP_RP (PREP_WP + 262144)       // 8,388,608 ints / 32
#define PREP_BLOCKS ((PREP_RP + 255) / 256)

__global__ void __launch_bounds__(256) prep_kernel(
    const float4* __restrict__ X, const float4* __restrict__ Wq,
    const float4* __restrict__ Wp, const int4* __restrict__ rp)
{
    int idx = blockIdx.x * 256 + threadIdx.x;
    if (idx < PREP_WP) {
        const float4* src;
        uint4* dst;
        int i;
        if (idx < PREP_X)       { src = X;  dst = (uint4*)g_ah; i = idx; }
        else if (idx < PREP_WQ) { src = Wq; dst = (uint4*)g_wq; i = idx - PREP_X; }
        else                    { src = Wp; dst = (uint4*)g_wp; i = idx - PREP_WQ; }
        float4 a = src[i * 2], b = src[i * 2 + 1];
        __half2 h0 = __floats2half2_rn(a.x, a.y);
        __half2 h1 = __floats2half2_rn(a.z, a.w);
        __half2 h2 = __floats2half2_rn(b.x, b.y);
        __half2 h3 = __floats2half2_rn(b.z, b.w);
        dst[i] = make_uint4(*(uint32_t*)&h0, *(uint32_t*)&h1,
                            *(uint32_t*)&h2, *(uint32_t*)&h3);
    } else if (idx < PREP_RP) {
        int gI = idx - PREP_WP;
        int r[32];
        #pragma unroll
        for (int i = 0; i < 8; i++) {
            int4 v = rp[gI * 8 + i];
            r[i*4+0] = v.x; r[i*4+1] = v.y; r[i*4+2] = v.z; r[i*4+3] = v.w;
        }
        uint32_t w[4];
        #pragma unroll
        for (int t = 0; t < 4; t++) {
            uint32_t acc = 0;
            #pragma unroll
            for (int nt = 0; nt < 4; nt++) {
                uint32_t pair = (uint32_t)r[8*nt + 2*t] | ((uint32_t)r[8*nt + 2*t + 1] << 4);
                acc |= pair << (8 * nt);
            }
            w[t] = acc;
        }
        ((uint4*)g_rpn)[gI] = make_uint4(w[0], w[1], w[2], w[3]);
    }
}

// ---------------------------------------------------------------------------
// fp16 tensor-core GEMM: C[M,N] = A[M,256] @ W[256,N]
// A tiles ldsm4 (row-major), B tiles ldsm4t from raw [K][N] fp16.
// block 128x128, K-chunks of 64, cp.async double buffer.
// ---------------------------------------------------------------------------
#define A_ROWB 144                       // 64 halves + pad
#define B_ROWB 272                       // 128 halves + pad
#define A_TILEB (128 * A_ROWB)           // 18432
#define B_TILEB (64 * B_ROWB)            // 17408
#define G_BUFB  (A_TILEB + B_TILEB)      // 35840
#define GEMM_SMEM (2 * G_BUFB)           // 71680

template<bool PROJ>
__global__ void __launch_bounds__(256, 2) gemm_f16_kernel(
    const uint4* __restrict__ A4, const __half* __restrict__ Bh, int ldb,
    float* __restrict__ outp, const float* __restrict__ bias)
{
    extern __shared__ char smem[];
    const int tid  = threadIdx.x;
    const int warp = tid >> 5, lane = tid & 31;
    const int g = lane >> 2, t = lane & 3;
    const int m0 = blockIdx.y * 128, n0 = blockIdx.x * 128;
    const int wm = warp >> 2, wn = warp & 3;     // 2x4 warps: 64 rows x 32 cols
    const uint32_t sb = smem_u32(smem);
    const int arow = lane & 15, chi = lane >> 4;

    float acc[4][4][4];
    #pragma unroll
    for (int mt = 0; mt < 4; mt++)
        #pragma unroll
        for (int nt = 0; nt < 4; nt++)
            #pragma unroll
            for (int r = 0; r < 4; r++) acc[mt][nt][r] = 0.f;

    auto load_chunk = [&](int c, int buf) {
        uint32_t base = sb + buf * G_BUFB;
        #pragma unroll
        for (int i = 0; i < 4; i++) {           // A: 1024 cp16
            int idx = i * 256 + tid;
            int row = idx >> 3, cc = idx & 7;
            cp16(base + row * A_ROWB + cc * 16,
                 &A4[(long)(m0 + row) * 32 + c * 8 + cc]);
        }
        #pragma unroll
        for (int i = 0; i < 4; i++) {           // B: 1024 cp16
            int idx = i * 256 + tid;
            int row = idx >> 4, cc = idx & 15;
            cp16(base + A_TILEB + row * B_ROWB + cc * 16,
                 Bh + (long)(c * 64 + row) * ldb + n0 + cc * 8);
        }
        cp_commit();
    };

    load_chunk(0, 0);

    for (int c = 0; c < 4; c++) {
        cp_wait0();
        __syncthreads();
        if (c < 3) load_chunk(c + 1, (c + 1) & 1);
        const uint32_t base = sb + (c & 1) * G_BUFB;
        const uint32_t bbase = base + A_TILEB;

        #pragma unroll
        for (int ks2 = 0; ks2 < 2; ks2++) {
            uint32_t bt[4][4];
            #pragma unroll
            for (int oct = 0; oct < 4; oct++)
                ldsm4t(bt[oct], bbase + (uint32_t)((ks2 * 32 + lane) * B_ROWB
                                                   + wn * 64 + oct * 16));
            #pragma unroll
            for (int r = 0; r < 2; r++) {
                uint32_t af[4][4];
                int s = ks2 * 2 + r;
                #pragma unroll
                for (int mt = 0; mt < 4; mt++)
                    ldsm4(af[mt], base + (uint32_t)((wm * 64 + mt * 16 + arow) * A_ROWB
                                                    + (2 * s + chi) * 16));
                #pragma unroll
                for (int mt = 0; mt < 4; mt++)
                    #pragma unroll
                    for (int nt = 0; nt < 4; nt++) {
                        uint32_t bb[2] = { bt[nt][2 * r], bt[nt][2 * r + 1] };
                        mma_f16(acc[mt][nt], af[mt], bb);
                    }
            }
        }
        __syncthreads();
    }

    if (PROJ) {
        #pragma unroll
        for (int mt = 0; mt < 4; mt++) {
            int m = m0 + wm * 64 + mt * 16 + g;
            #pragma unroll
            for (int nt = 0; nt < 4; nt++) {
                int col = n0 + wn * 32 + nt * 8 + 2 * t;
                float b0 = bias[col], b1 = bias[col + 1];
                *(float2*)&outp[(long)m * 256 + col] =
                    make_float2(acc[mt][nt][0] + b0, acc[mt][nt][1] + b1);
                *(float2*)&outp[(long)(m + 8) * 256 + col] =
                    make_float2(acc[mt][nt][2] + b0, acc[mt][nt][3] + b1);
            }
        }
    } else {
        const float scale = 0.25503483f;   // 32^-0.5 * log2(e)
        #pragma unroll
        for (int mt = 0; mt < 4; mt++) {
            int m = m0 + wm * 64 + mt * 16 + g;
            int bb = m >> 10, nn = m & 1023;
            #pragma unroll
            for (int nt = 0; nt < 4; nt++) {
                int col = n0 + wn * 32 + nt * 8 + 2 * t;
                int sel = col >> 8, hh = (col >> 5) & 7, dd = col & 31;
                float c0 = acc[mt][nt][0], c1 = acc[mt][nt][1];
                float c2 = acc[mt][nt][2], c3 = acc[mt][nt][3];
                if (sel == 0) { c0 *= scale; c1 *= scale; c2 *= scale; c3 *= scale; }
                __half* dst = (sel == 0) ? g_qh : (sel == 1) ? g_kh : g_vh;
                long base = (((long)bb * HH + hh) * NN + nn) * HD + dd;
                *(__half2*)&dst[base]           = __floats2half2_rn(c0, c1);
                *(__half2*)&dst[base + 8 * HD]  = __floats2half2_rn(c2, c3);
            }
        }
    }
}

// ---------------------------------------------------------------------------
// Fused flash attention v5: warp-autonomous, zero block barriers,
// fixed-shift ex2 softmax, bias via LDS.32 packed-nibble + pair table.
// ---------------------------------------------------------------------------
#define AKROWB 80
#define AKTILE (32 * AKROWB)             // 2560
#define ASTAGE (2 * AKTILE + 512)        // K + V + rpn = 5632
#define AWARP  (2 * ASTAGE + 640)        // 2 stages + table = 11904
#define ATT_SMEM (8 * AWARP)             // 95232
#define SOFT_SHIFT 4.0f

__global__ void __launch_bounds__(256, 2) attn_mma_kernel(
    const int* __restrict__ rel_len, const float* __restrict__ bias_table)
{
    extern __shared__ char smc[];

    const int tid  = threadIdx.x;
    const int h    = tid >> 5;
    const int lane = tid & 31;
    const int g    = lane >> 2;
    const int t    = lane & 3;
    const int b    = blockIdx.x >> 5;
    const int row0 = (blockIdx.x & 31) * 32;

    char* smw = smc + h * AWARP;
    const uint32_t sbw = smem_u32(smw);
    uint32_t* tblp = (uint32_t*)(smw + 2 * ASTAGE);

    // per-head masked bias table (log2 domain) -> pair table
    {
        const int mask_len = (int)(__int2float_rn(rel_len[b]) * 0.5f);
        float btl2 = 0.f;
        if (lane < TABLE)
            btl2 = bias_table[lane * HH + h] * 1.4426950408889634f
                 + ((lane > mask_len) ? -144.2695040888963f : 0.f);
        #pragma unroll
        for (int i = lane; i < 160; i += 32) {
            float lo = __shfl_sync(0xffffffffu, btl2, i & 15);
            float hi = __shfl_sync(0xffffffffu, btl2, i >> 4);
            tblp[i] = pack2(lo, hi);
        }
    }

    // V pad columns (d=32..39) = fp16 ones, both stages
    {
        const uint4 ones = make_uint4(0x3C003C00u, 0x3C003C00u, 0x3C003C00u, 0x3C003C00u);
        #pragma unroll
        for (int i = 0; i < 2; i++) {
            int row = lane + i * 32;
            int stg = row >> 5, rem = row & 31;
            *(uint4*)(smw + stg * ASTAGE + AKTILE + rem * AKROWB + 64) = ones;
        }
    }

    // Q fragments (scale*log2e pre-folded)
    uint32_t qa[2][2][4];
    {
        const uint32_t* qw = (const uint32_t*)g_qh;
        long rbase = ((long)(b * HH) + h) * NN + row0;
        #pragma unroll
        for (int mt = 0; mt < 2; mt++) {
            long rA = (rbase + mt * 16 + g) * 16;
            long rB = rA + 8 * 16;
            #pragma unroll
            for (int ks = 0; ks < 2; ks++) {
                int w = ks * 8 + t;
                qa[mt][ks][0] = qw[rA + w];
                qa[mt][ks][1] = qw[rB + w];
                qa[mt][ks][2] = qw[rA + w + 4];
                qa[mt][ks][3] = qw[rB + w + 4];
            }
        }
    }

    float o[2][5][4];
    #pragma unroll
    for (int mt = 0; mt < 2; mt++)
        #pragma unroll
        for (int nt = 0; nt < 5; nt++)
            #pragma unroll
            for (int r = 0; r < 4; r++) o[mt][nt][r] = 0.f;

    const __half*  gk   = g_kh;
    const __half*  gv   = g_vh;
    const uint8_t* grpn = g_rpn;
    const long kvhead = ((long)(b * HH) + h) * NN * HD;
    const long rpnrow = ((long)b * NN + row0 + lane) * (NN / 2);

    auto prefetch = [&](int j, int stg) {
        uint32_t base = sbw + stg * ASTAGE;
        long src = kvhead + (long)(j * 32) * HD;
        #pragma unroll
        for (int i = 0; i < 4; i++) {
            int idx = i * 32 + lane;
            int row = idx >> 2, ch = idx & 3;
            uint32_t d = base + row * AKROWB + ch * 16;
            cp16(d, gk + src + row * HD + ch * 8);
            cp16(d + AKTILE, gv + src + row * HD + ch * 8);
        }
        cp16(base + 2 * AKTILE + lane * 16, grpn + rpnrow + j * 16);
        cp_commit();
    };

    prefetch(0, 0);

    const int ln8 = lane & 7, l8 = lane >> 3;

    for (int j = 0; j < 32; j++) {
        const int stg = j & 1;
        if (j + 1 < 32) { prefetch(j + 1, stg ^ 1); cp_wait1(); }
        else            { cp_wait0(); }

        const uint32_t kbase = sbw + stg * ASTAGE;
        const uint32_t vbase = kbase + AKTILE;
        const char*    rpn_s = smw + stg * ASTAGE + 2 * AKTILE;

        // ---- S = Q @ K^T, accumulator pre-loaded with -SHIFT ----
        float c[2][4][4];
        #pragma unroll
        for (int mt = 0; mt < 2; mt++)
            #pragma unroll
            for (int nt = 0; nt < 4; nt++)
                #pragma unroll
                for (int r = 0; r < 4; r++) c[mt][nt][r] = -SOFT_SHIFT;
        {
            uint32_t kb[4][4];
            uint32_t ka = kbase + (uint32_t)(ln8 * AKROWB + l8 * 16);
            #pragma unroll
            for (int nt = 0; nt < 4; nt++)
                ldsm4(kb[nt], ka + nt * (8 * AKROWB));
            #pragma unroll
            for (int nt = 0; nt < 4; nt++)
                #pragma unroll
                for (int ks = 0; ks < 2; ks++) {
                    uint32_t bf[2] = { kb[nt][2 * ks], kb[nt][2 * ks + 1] };
                    mma_f16(c[0][nt], qa[0][ks], bf);
                    mma_f16(c[1][nt], qa[1][ks], bf);
                }
        }

        // ---- V frags early (independent of softmax) ----
        uint32_t vb[5][4];
        {
            uint32_t va = vbase + (uint32_t)(lane * AKROWB);
            #pragma unroll
            for (int nt = 0; nt < 5; nt++)
                ldsm4t(vb[nt], va + nt * 16);
        }

        // ---- bias via packed LDS.32 + pair table, fixed-shift ex2 ----
        uint32_t pa[2][2][4];
        #pragma unroll
        for (int mt = 0; mt < 2; mt++) {
            int rA = mt * 16 + g, rB = rA + 8;
            uint32_t wA = *(const uint32_t*)(rpn_s + rA * 16 + t * 4);
            uint32_t wB = *(const uint32_t*)(rpn_s + rB * 16 + t * 4);
            uint32_t hA[4], hB[4];
            #pragma unroll
            for (int nt = 0; nt < 4; nt++) {
                uint32_t iA = (wA >> (8 * nt)) & 0xFF;
                uint32_t iB = (wB >> (8 * nt)) & 0xFF;
                hA[nt] = ex2h2(hadd2u(pack2(c[mt][nt][0], c[mt][nt][1]), tblp[iA]));
                hB[nt] = ex2h2(hadd2u(pack2(c[mt][nt][2], c[mt][nt][3]), tblp[iB]));
            }
            #pragma unroll
            for (int ks = 0; ks < 2; ks++) {
                pa[mt][ks][0] = hA[2 * ks];
                pa[mt][ks][1] = hB[2 * ks];
                pa[mt][ks][2] = hA[2 * ks + 1];
                pa[mt][ks][3] = hB[2 * ks + 1];
            }
        }

        // ---- O += P @ [V | 1] ----
        #pragma unroll
        for (int ks = 0; ks < 2; ks++)
            #pragma unroll
            for (int nt = 0; nt < 5; nt++) {
                uint32_t bf[2] = { vb[nt][2 * ks], vb[nt][2 * ks + 1] };
                mma_f16(o[0][nt], pa[0][ks], bf);
                mma_f16(o[1][nt], pa[1][ks], bf);
            }
    }

    // ---- epilogue: normalize by ones-column sums, store fp16 to g_xh ----
    #pragma unroll
    for (int mt = 0; mt < 2; mt++) {
        float i0 = 1.f / o[mt][4][0];
        float i1 = 1.f / o[mt][4][2];
        int rA = row0 + mt * 16 + g;
        #pragma unroll
        for (int nt = 0; nt < 4; nt++) {
            int col = h * HD + nt * 8 + 2 * t;
            *(__half2*)&g_xh[((long)b * NN + rA) * CC + col] =
                __floats2half2_rn(o[mt][nt][0] * i0, o[mt][nt][1] * i0);
            *(__half2*)&g_xh[((long)b * NN + rA + 8) * CC + col] =
                __floats2half2_rn(o[mt][nt][2] * i1, o[mt][nt][3] * i1);
        }
    }
}

// ---------------------------------------------------------------------------
extern "C" void kernel_launch(void* const* d_in, const int* in_sizes, int n_in,
                              void* d_out, int out_size)
{
    const float* X       = (const float*)d_in[0];
    const int*   rp      = (const int*)  d_in[1];
    const int*   rel_len = (const int*)  d_in[2];
    const float* Wqkv    = (const float*)d_in[3];
    const float* Wproj   = (const float*)d_in[4];
    const float* bproj   = (const float*)d_in[5];
    const float* btab    = (const float*)d_in[6];
    float* out = (float*)d_out;

    __half* d_ah;  cudaGetSymbolAddress((void**)&d_ah, g_ah);
    __half* d_wq;  cudaGetSymbolAddress((void**)&d_wq, g_wq);
    __half* d_wp;  cudaGetSymbolAddress((void**)&d_wp, g_wp);
    __half* d_xh;  cudaGetSymbolAddress((void**)&d_xh, g_xh);

    // 1) fused prep: converts + rp nibble pack
    prep_kernel<<<PREP_BLOCKS, 256>>>((const float4*)X, (const float4*)Wqkv,
                                      (const float4*)Wproj, (const int4*)rp);

    // 2) qkv GEMM (fp16 MMA, B via ldsm.trans from raw [K][N])
    cudaFuncSetAttribute(gemm_f16_kernel<false>,
                         cudaFuncAttributeMaxDynamicSharedMemorySize, GEMM_SMEM);
    gemm_f16_kernel<false><<<dim3(6, 64), 256, GEMM_SMEM>>>(
        (const uint4*)d_ah, d_wq, 768, nullptr, nullptr);

    // 3) attention
    cudaFuncSetAttribute(attn_mma_kernel,
                         cudaFuncAttributeMaxDynamicSharedMemorySize, ATT_SMEM);
    attn_mma_kernel<<<BB * 32, 256, ATT_SMEM>>>(rel_len, btab);

    // 4) proj GEMM + bias -> fp32 out
    cudaFuncSetAttribute(gemm_f16_kernel<true>,
                         cudaFuncAttributeMaxDynamicSharedMemorySize, GEMM_SMEM);
    gemm_f16_kernel<true><<<dim3(2, 64), 256, GEMM_SMEM>>>(
        (const uint4*)d_xh, d_wp, 256, out, bproj);
}

// round 11
// speedup vs baseline: 1.6667x; 1.0682x over previous
#include <cuda_runtime.h>
#include <cuda_fp16.h>
#include <cstdint>

#define BB 8
#define NN 1024
#define CC 256
#define HH 8
#define HD 32
#define TABLE 10

// Scratch (allocation-free rule: __device__ globals)
__device__ __half   g_ah [BB*NN*CC];      // X fp16 [8192][256]
__device__ __half   g_wq [3*CC*CC];       // W_qkv fp16 [256][768]  (raw layout)
__device__ __half   g_wp [CC*CC];         // W_proj fp16 [256][256] (raw layout)
__device__ __half   g_qh [BB*HH*NN*HD];   // q * scale * log2e, fp16
__device__ __half   g_kh [BB*HH*NN*HD];
__device__ __half   g_vh [BB*HH*NN*HD];
__device__ __half   g_xh [BB*NN*CC];      // attention output fp16 [8192][256]
__device__ uint8_t  g_rpn[BB*NN*NN/2];    // rp nibble-packed, bytes permuted t*4+nt

// ---------------------------------------------------------------------------
// helpers
// ---------------------------------------------------------------------------
__device__ __forceinline__ void mma_f16(float* c, const uint32_t* a, const uint32_t* b) {
    asm volatile(
        "mma.sync.aligned.m16n8k16.row.col.f32.f16.f16.f32 "
        "{%0,%1,%2,%3},{%4,%5,%6,%7},{%8,%9},{%0,%1,%2,%3};\n"
        : "+f"(c[0]), "+f"(c[1]), "+f"(c[2]), "+f"(c[3])
        : "r"(a[0]), "r"(a[1]), "r"(a[2]), "r"(a[3]), "r"(b[0]), "r"(b[1]));
}
__device__ __forceinline__ void ldsm4(uint32_t* r, uint32_t addr) {
    asm volatile("ldmatrix.sync.aligned.m8n8.x4.shared.b16 {%0,%1,%2,%3},[%4];"
                 : "=r"(r[0]), "=r"(r[1]), "=r"(r[2]), "=r"(r[3]) : "r"(addr));
}
__device__ __forceinline__ void ldsm4t(uint32_t* r, uint32_t addr) {
    asm volatile("ldmatrix.sync.aligned.m8n8.x4.trans.shared.b16 {%0,%1,%2,%3},[%4];"
                 : "=r"(r[0]), "=r"(r[1]), "=r"(r[2]), "=r"(r[3]) : "r"(addr));
}
__device__ __forceinline__ uint32_t smem_u32(const void* p) {
    uint32_t a;
    asm("{ .reg .u64 t; cvta.to.shared.u64 t, %1; cvt.u32.u64 %0, t; }" : "=r"(a) : "l"(p));
    return a;
}
__device__ __forceinline__ void cp16(uint32_t dst, const void* src) {
    asm volatile("cp.async.ca.shared.global [%0],[%1],16;" :: "r"(dst), "l"(src));
}
__device__ __forceinline__ void cp_commit() { asm volatile("cp.async.commit_group;"); }
__device__ __forceinline__ void cp_wait0()  { asm volatile("cp.async.wait_group 0;"); }
__device__ __forceinline__ uint32_t ex2h2(uint32_t x) {
    uint32_t r;
    asm("ex2.approx.f16x2 %0, %1;" : "=r"(r) : "r"(x));
    return r;
}
__device__ __forceinline__ uint32_t hadd2u(uint32_t a, uint32_t b) {
    __half2 r = __hadd2(*(__half2*)&a, *(__half2*)&b);
    return *(uint32_t*)&r;
}
__device__ __forceinline__ uint32_t pack2(float lo, float hi) {
    __half2 h = __floats2half2_rn(lo, hi);
    return *(uint32_t*)&h;
}

// ---------------------------------------------------------------------------
// Fused prep: X->fp16, Wqkv->fp16, Wproj->fp16, rp nibble-pack (permuted).
// ---------------------------------------------------------------------------
#define PREP_X  262144
#define PREP_WQ (PREP_X + 24576)
#define PREP_WP (PREP_WQ + 8192)
#define PREP_RP (PREP_WP + 262144)
#define PREP_BLOCKS ((PREP_RP + 255) / 256)

__global__ void __launch_bounds__(256) prep_kernel(
    const float4* __restrict__ X, const float4* __restrict__ Wq,
    const float4* __restrict__ Wp, const int4* __restrict__ rp)
{
    int idx = blockIdx.x * 256 + threadIdx.x;
    if (idx < PREP_WP) {
        const float4* src;
        uint4* dst;
        int i;
        if (idx < PREP_X)       { src = X;  dst = (uint4*)g_ah; i = idx; }
        else if (idx < PREP_WQ) { src = Wq; dst = (uint4*)g_wq; i = idx - PREP_X; }
        else                    { src = Wp; dst = (uint4*)g_wp; i = idx - PREP_WQ; }
        float4 a = src[i * 2], b = src[i * 2 + 1];
        __half2 h0 = __floats2half2_rn(a.x, a.y);
        __half2 h1 = __floats2half2_rn(a.z, a.w);
        __half2 h2 = __floats2half2_rn(b.x, b.y);
        __half2 h3 = __floats2half2_rn(b.z, b.w);
        dst[i] = make_uint4(*(uint32_t*)&h0, *(uint32_t*)&h1,
                            *(uint32_t*)&h2, *(uint32_t*)&h3);
    } else if (idx < PREP_RP) {
        int gI = idx - PREP_WP;
        int r[32];
        #pragma unroll
        for (int i = 0; i < 8; i++) {
            int4 v = rp[gI * 8 + i];
            r[i*4+0] = v.x; r[i*4+1] = v.y; r[i*4+2] = v.z; r[i*4+3] = v.w;
        }
        uint32_t w[4];
        #pragma unroll
        for (int t = 0; t < 4; t++) {
            uint32_t acc = 0;
            #pragma unroll
            for (int nt = 0; nt < 4; nt++) {
                uint32_t pair = (uint32_t)r[8*nt + 2*t] | ((uint32_t)r[8*nt + 2*t + 1] << 4);
                acc |= pair << (8 * nt);
            }
            w[t] = acc;
        }
        ((uint4*)g_rpn)[gI] = make_uint4(w[0], w[1], w[2], w[3]);
    }
}

// ---------------------------------------------------------------------------
// fp16 tensor-core GEMM: C[M,N] = A[M,256] @ W[256,N]
// block tile 64x128, K-chunks of 64, cp.async double buffer. 8 warps (2x4),
// warp tile 32x32. More blocks in flight than the old 128x128 version.
// ---------------------------------------------------------------------------
#define A_ROWB 144                       // 64 halves + pad
#define B_ROWB 272                       // 128 halves + pad
#define A_TILEB (64 * A_ROWB)            // 9216
#define B_TILEB (64 * B_ROWB)            // 17408
#define G_BUFB  (A_TILEB + B_TILEB)      // 26624
#define GEMM_SMEM (2 * G_BUFB)           // 53248

template<bool PROJ>
__global__ void __launch_bounds__(256) gemm_f16_kernel(
    const uint4* __restrict__ A4, const __half* __restrict__ Bh, int ldb,
    float* __restrict__ outp, const float* __restrict__ bias)
{
    extern __shared__ char smem[];
    const int tid  = threadIdx.x;
    const int warp = tid >> 5, lane = tid & 31;
    const int g = lane >> 2, t = lane & 3;
    const int m0 = blockIdx.y * 64, n0 = blockIdx.x * 128;
    const int wm = warp >> 2, wn = warp & 3;     // 2x4 warps: 32 rows x 32 cols
    const uint32_t sb = smem_u32(smem);
    const int arow = lane & 15, chi = lane >> 4;

    float acc[2][4][4];
    #pragma unroll
    for (int mt = 0; mt < 2; mt++)
        #pragma unroll
        for (int nt = 0; nt < 4; nt++)
            #pragma unroll
            for (int r = 0; r < 4; r++) acc[mt][nt][r] = 0.f;

    auto load_chunk = [&](int c, int buf) {
        uint32_t base = sb + buf * G_BUFB;
        #pragma unroll
        for (int i = 0; i < 2; i++) {           // A: 512 cp16
            int idx = i * 256 + tid;
            int row = idx >> 3, cc = idx & 7;
            cp16(base + row * A_ROWB + cc * 16,
                 &A4[(long)(m0 + row) * 32 + c * 8 + cc]);
        }
        #pragma unroll
        for (int i = 0; i < 4; i++) {           // B: 1024 cp16
            int idx = i * 256 + tid;
            int row = idx >> 4, cc = idx & 15;
            cp16(base + A_TILEB + row * B_ROWB + cc * 16,
                 Bh + (long)(c * 64 + row) * ldb + n0 + cc * 8);
        }
        cp_commit();
    };

    load_chunk(0, 0);

    for (int c = 0; c < 4; c++) {
        cp_wait0();
        __syncthreads();
        if (c < 3) load_chunk(c + 1, (c + 1) & 1);
        const uint32_t base = sb + (c & 1) * G_BUFB;
        const uint32_t bbase = base + A_TILEB;

        #pragma unroll
        for (int ks2 = 0; ks2 < 2; ks2++) {
            uint32_t bt[4][4];
            #pragma unroll
            for (int oct = 0; oct < 4; oct++)
                ldsm4t(bt[oct], bbase + (uint32_t)((ks2 * 32 + lane) * B_ROWB
                                                   + wn * 64 + oct * 16));
            #pragma unroll
            for (int r = 0; r < 2; r++) {
                uint32_t af[2][4];
                int s = ks2 * 2 + r;
                #pragma unroll
                for (int mt = 0; mt < 2; mt++)
                    ldsm4(af[mt], base + (uint32_t)((wm * 32 + mt * 16 + arow) * A_ROWB
                                                    + (2 * s + chi) * 16));
                #pragma unroll
                for (int mt = 0; mt < 2; mt++)
                    #pragma unroll
                    for (int nt = 0; nt < 4; nt++) {
                        uint32_t bb[2] = { bt[nt][2 * r], bt[nt][2 * r + 1] };
                        mma_f16(acc[mt][nt], af[mt], bb);
                    }
            }
        }
        __syncthreads();
    }

    if (PROJ) {
        #pragma unroll
        for (int mt = 0; mt < 2; mt++) {
            int m = m0 + wm * 32 + mt * 16 + g;
            #pragma unroll
            for (int nt = 0; nt < 4; nt++) {
                int col = n0 + wn * 32 + nt * 8 + 2 * t;
                float b0 = bias[col], b1 = bias[col + 1];
                *(float2*)&outp[(long)m * 256 + col] =
                    make_float2(acc[mt][nt][0] + b0, acc[mt][nt][1] + b1);
                *(float2*)&outp[(long)(m + 8) * 256 + col] =
                    make_float2(acc[mt][nt][2] + b0, acc[mt][nt][3] + b1);
            }
        }
    } else {
        const float scale = 0.25503483f;   // 32^-0.5 * log2(e)
        #pragma unroll
        for (int mt = 0; mt < 2; mt++) {
            int m = m0 + wm * 32 + mt * 16 + g;
            int bb = m >> 10, nn = m & 1023;
            #pragma unroll
            for (int nt = 0; nt < 4; nt++) {
                int col = n0 + wn * 32 + nt * 8 + 2 * t;
                int sel = col >> 8, hh = (col >> 5) & 7, dd = col & 31;
                float c0 = acc[mt][nt][0], c1 = acc[mt][nt][1];
                float c2 = acc[mt][nt][2], c3 = acc[mt][nt][3];
                if (sel == 0) { c0 *= scale; c1 *= scale; c2 *= scale; c3 *= scale; }
                __half* dst = (sel == 0) ? g_qh : (sel == 1) ? g_kh : g_vh;
                long base = (((long)bb * HH + hh) * NN + nn) * HD + dd;
                *(__half2*)&dst[base]           = __floats2half2_rn(c0, c1);
                *(__half2*)&dst[base + 8 * HD]  = __floats2half2_rn(c2, c3);
            }
        }
    }
}

// ---------------------------------------------------------------------------
// Fused flash attention v6: block = (batch, head, 64 q-rows), 4 warps x 16 rows.
// K/V tile shared by 4 warps (halves L2 traffic vs v5), one barrier per tile,
// ~13 KB smem/block -> ~5 blocks/SM. Fixed-shift ex2 softmax, ones-column sums.
// ---------------------------------------------------------------------------
#define AKROWB 80
#define AKTILE (32 * AKROWB)             // 2560
#define ASTAGE (2 * AKTILE + 1024)       // K + V + rpn(64 rows) = 6144
#define ATT_SMEM (2 * ASTAGE + 640)      // 12928
#define SOFT_SHIFT 4.0f

__global__ void __launch_bounds__(128, 4) attn_mma_kernel(
    const int* __restrict__ rel_len, const float* __restrict__ bias_table)
{
    extern __shared__ char smc[];
    const uint32_t sb = smem_u32(smc);

    const int tid  = threadIdx.x;
    const int w    = tid >> 5;               // warp 0..3 -> 16-row m-tile
    const int lane = tid & 31;
    const int g    = lane >> 2;
    const int t    = lane & 3;
    const int b     = blockIdx.x >> 7;
    const int h     = (blockIdx.x >> 4) & 7;
    const int chunk = blockIdx.x & 15;
    const int row0  = chunk * 64;

    uint32_t* tblp = (uint32_t*)(smc + 2 * ASTAGE);

    // per-head masked bias pair table (log2 domain), built by all 128 threads
    {
        const int mask_len = (int)(__int2float_rn(rel_len[b]) * 0.5f);
        for (int i = tid; i < 160; i += 128) {
            int lo = i & 15, hi = i >> 4;
            float vlo = (lo < TABLE)
                ? bias_table[lo * HH + h] * 1.4426950408889634f
                  + ((lo > mask_len) ? -144.2695040888963f : 0.f) : 0.f;
            float vhi = bias_table[hi * HH + h] * 1.4426950408889634f
                  + ((hi > mask_len) ? -144.2695040888963f : 0.f);
            tblp[i] = pack2(vlo, vhi);
        }
    }
    // V pad columns (d=32..39) = fp16 ones, both stages
    if (tid < 64) {
        const uint4 ones = make_uint4(0x3C003C00u, 0x3C003C00u, 0x3C003C00u, 0x3C003C00u);
        int stg = tid >> 5, row = tid & 31;
        *(uint4*)(smc + stg * ASTAGE + AKTILE + row * AKROWB + 64) = ones;
    }

    // Q fragments: warp w's 16 rows (scale*log2e pre-folded)
    uint32_t qa[2][4];
    {
        const uint32_t* qw = (const uint32_t*)g_qh;
        long rbase = (((long)(b * HH) + h) * NN + row0 + w * 16);
        long rA = (rbase + g) * 16, rB = rA + 128;
        #pragma unroll
        for (int ks = 0; ks < 2; ks++) {
            int wd = ks * 8 + t;
            qa[ks][0] = qw[rA + wd];
            qa[ks][1] = qw[rB + wd];
            qa[ks][2] = qw[rA + wd + 4];
            qa[ks][3] = qw[rB + wd + 4];
        }
    }

    float o[5][4];                           // nt=4 is ones column (row sums)
    #pragma unroll
    for (int nt = 0; nt < 5; nt++)
        #pragma unroll
        for (int r = 0; r < 4; r++) o[nt][r] = 0.f;

    const __half*  gk   = g_kh;
    const __half*  gv   = g_vh;
    const uint8_t* grpn = g_rpn;
    const long kvhead = ((long)(b * HH) + h) * NN * HD;
    const long rpnrow = ((long)b * NN + row0) * (NN / 2);

    // cooperative prefetch of tile j into stage stg (128 threads)
    auto prefetch = [&](int j, int stg) {
        uint32_t base = sb + stg * ASTAGE;
        long src = kvhead + (long)(j * 32) * HD;
        int row = tid >> 2, ch = tid & 3;    // 128 threads -> 32 rows x 4 chunks
        uint32_t d = base + row * AKROWB + ch * 16;
        cp16(d, gk + src + row * HD + ch * 8);
        cp16(d + AKTILE, gv + src + row * HD + ch * 8);
        if (tid < 64)
            cp16(base + 2 * AKTILE + tid * 16, grpn + rpnrow + (long)tid * 512 + j * 16);
        cp_commit();
    };

    prefetch(0, 0);

    const int ln8 = lane & 7, l8 = lane >> 3;
    const int rAr = w * 16 + g;              // rpn row of frag rows 0,1

    for (int j = 0; j < 32; j++) {
        const int stg = j & 1;
        cp_wait0();
        __syncthreads();                     // stage stg ready; stage stg^1 free
        if (j < 31) prefetch(j + 1, stg ^ 1);

        const uint32_t kbase = sb + stg * ASTAGE;
        const uint32_t vbase = kbase + AKTILE;
        const char*    rpn_s = smc + stg * ASTAGE + 2 * AKTILE;

        // ---- S = Q @ K^T, accumulator pre-loaded with -SHIFT ----
        float c[4][4];
        #pragma unroll
        for (int nt = 0; nt < 4; nt++)
            #pragma unroll
            for (int r = 0; r < 4; r++) c[nt][r] = -SOFT_SHIFT;
        {
            uint32_t kb[4][4];
            uint32_t ka = kbase + (uint32_t)(ln8 * AKROWB + l8 * 16);
            #pragma unroll
            for (int nt = 0; nt < 4; nt++)
                ldsm4(kb[nt], ka + nt * (8 * AKROWB));
            #pragma unroll
            for (int nt = 0; nt < 4; nt++)
                #pragma unroll
                for (int ks = 0; ks < 2; ks++) {
                    uint32_t bf[2] = { kb[nt][2 * ks], kb[nt][2 * ks + 1] };
                    mma_f16(c[nt], qa[ks], bf);
                }
        }

        // ---- V frags (independent of softmax) ----
        uint32_t vb[5][4];
        {
            uint32_t va = vbase + (uint32_t)(lane * AKROWB);
            #pragma unroll
            for (int nt = 0; nt < 5; nt++)
                ldsm4t(vb[nt], va + nt * 16);
        }

        // ---- bias via packed LDS.32 + pair table, fixed-shift ex2 ----
        uint32_t pa[2][4];
        {
            uint32_t wA = *(const uint32_t*)(rpn_s + rAr * 16 + t * 4);
            uint32_t wB = *(const uint32_t*)(rpn_s + (rAr + 8) * 16 + t * 4);
            uint32_t hA[4], hB[4];
            #pragma unroll
            for (int nt = 0; nt < 4; nt++) {
                uint32_t iA = (wA >> (8 * nt)) & 0xFF;
                uint32_t iB = (wB >> (8 * nt)) & 0xFF;
                hA[nt] = ex2h2(hadd2u(pack2(c[nt][0], c[nt][1]), tblp[iA]));
                hB[nt] = ex2h2(hadd2u(pack2(c[nt][2], c[nt][3]), tblp[iB]));
            }
            #pragma unroll
            for (int ks = 0; ks < 2; ks++) {
                pa[ks][0] = hA[2 * ks];
                pa[ks][1] = hB[2 * ks];
                pa[ks][2] = hA[2 * ks + 1];
                pa[ks][3] = hB[2 * ks + 1];
            }
        }

        // ---- O += P @ [V | 1] ----
        #pragma unroll
        for (int ks = 0; ks < 2; ks++)
            #pragma unroll
            for (int nt = 0; nt < 5; nt++) {
                uint32_t bf[2] = { vb[nt][2 * ks], vb[nt][2 * ks + 1] };
                mma_f16(o[nt], pa[ks], bf);
            }
    }

    // ---- epilogue: normalize by ones-column sums, store fp16 to g_xh ----
    {
        float i0 = 1.f / o[4][0];
        float i1 = 1.f / o[4][2];
        int rA = row0 + w * 16 + g;
        #pragma unroll
        for (int nt = 0; nt < 4; nt++) {
            int col = h * HD + nt * 8 + 2 * t;
            *(__half2*)&g_xh[((long)b * NN + rA) * CC + col] =
                __floats2half2_rn(o[nt][0] * i0, o[nt][1] * i0);
            *(__half2*)&g_xh[((long)b * NN + rA + 8) * CC + col] =
                __floats2half2_rn(o[nt][2] * i1, o[nt][3] * i1);
        }
    }
}

// ---------------------------------------------------------------------------
extern "C" void kernel_launch(void* const* d_in, const int* in_sizes, int n_in,
                              void* d_out, int out_size)
{
    const float* X       = (const float*)d_in[0];
    const int*   rp      = (const int*)  d_in[1];
    const int*   rel_len = (const int*)  d_in[2];
    const float* Wqkv    = (const float*)d_in[3];
    const float* Wproj   = (const float*)d_in[4];
    const float* bproj   = (const float*)d_in[5];
    const float* btab    = (const float*)d_in[6];
    float* out = (float*)d_out;

    __half* d_ah;  cudaGetSymbolAddress((void**)&d_ah, g_ah);
    __half* d_wq;  cudaGetSymbolAddress((void**)&d_wq, g_wq);
    __half* d_wp;  cudaGetSymbolAddress((void**)&d_wp, g_wp);
    __half* d_xh;  cudaGetSymbolAddress((void**)&d_xh, g_xh);

    // 1) fused prep: converts + rp nibble pack
    prep_kernel<<<PREP_BLOCKS, 256>>>((const float4*)X, (const float4*)Wqkv,
                                      (const float4*)Wproj, (const int4*)rp);

    // 2) qkv GEMM (64x128 tiles, 768 blocks)
    cudaFuncSetAttribute(gemm_f16_kernel<false>,
                         cudaFuncAttributeMaxDynamicSharedMemorySize, GEMM_SMEM);
    gemm_f16_kernel<false><<<dim3(6, 128), 256, GEMM_SMEM>>>(
        (const uint4*)d_ah, d_wq, 768, nullptr, nullptr);

    // 3) attention (1024 blocks x 128 threads)
    attn_mma_kernel<<<BB * HH * 16, 128, ATT_SMEM>>>(rel_len, btab);

    // 4) proj GEMM (64x128 tiles, 256 blocks) + bias -> fp32 out
    cudaFuncSetAttribute(gemm_f16_kernel<true>,
                         cudaFuncAttributeMaxDynamicSharedMemorySize, GEMM_SMEM);
    gemm_f16_kernel<true><<<dim3(2, 128), 256, GEMM_SMEM>>>(
        (const uint4*)d_xh, d_wp, 256, out, bproj);
}

// round 12
// speedup vs baseline: 1.8233x; 1.0940x over previous
#include <cuda_runtime.h>
#include <cuda_fp16.h>
#include <cstdint>

#define BB 8
#define NN 1024
#define CC 256
#define HH 8
#define HD 32
#define TABLE 10

// Scratch (allocation-free rule: __device__ globals)
__device__ __half   g_ah [BB*NN*CC];      // X fp16 [8192][256]
__device__ __half   g_wq [3*CC*CC];       // W_qkv fp16 [256][768]  (raw layout)
__device__ __half   g_wp [CC*CC];         // W_proj fp16 [256][256] (raw layout)
__device__ __half   g_qh [BB*HH*NN*HD];   // q * scale * log2e, fp16
__device__ __half   g_kh [BB*HH*NN*HD];
__device__ __half   g_vh [BB*HH*NN*HD];
__device__ __half   g_xh [BB*NN*CC];      // attention output fp16 [8192][256]
__device__ uint8_t  g_rpn[BB*NN*NN/2];    // rp nibble-packed, bytes permuted t*4+nt

// ---------------------------------------------------------------------------
// helpers
// ---------------------------------------------------------------------------
__device__ __forceinline__ void mma_f16(float* c, const uint32_t* a, const uint32_t* b) {
    asm volatile(
        "mma.sync.aligned.m16n8k16.row.col.f32.f16.f16.f32 "
        "{%0,%1,%2,%3},{%4,%5,%6,%7},{%8,%9},{%0,%1,%2,%3};\n"
        : "+f"(c[0]), "+f"(c[1]), "+f"(c[2]), "+f"(c[3])
        : "r"(a[0]), "r"(a[1]), "r"(a[2]), "r"(a[3]), "r"(b[0]), "r"(b[1]));
}
__device__ __forceinline__ void ldsm4(uint32_t* r, uint32_t addr) {
    asm volatile("ldmatrix.sync.aligned.m8n8.x4.shared.b16 {%0,%1,%2,%3},[%4];"
                 : "=r"(r[0]), "=r"(r[1]), "=r"(r[2]), "=r"(r[3]) : "r"(addr));
}
__device__ __forceinline__ void ldsm4t(uint32_t* r, uint32_t addr) {
    asm volatile("ldmatrix.sync.aligned.m8n8.x4.trans.shared.b16 {%0,%1,%2,%3},[%4];"
                 : "=r"(r[0]), "=r"(r[1]), "=r"(r[2]), "=r"(r[3]) : "r"(addr));
}
__device__ __forceinline__ uint32_t smem_u32(const void* p) {
    uint32_t a;
    asm("{ .reg .u64 t; cvta.to.shared.u64 t, %1; cvt.u32.u64 %0, t; }" : "=r"(a) : "l"(p));
    return a;
}
__device__ __forceinline__ void cp16(uint32_t dst, const void* src) {
    asm volatile("cp.async.ca.shared.global [%0],[%1],16;" :: "r"(dst), "l"(src));
}
__device__ __forceinline__ void cp_commit() { asm volatile("cp.async.commit_group;"); }
__device__ __forceinline__ void cp_wait0()  { asm volatile("cp.async.wait_group 0;"); }
__device__ __forceinline__ uint32_t ex2h2(uint32_t x) {
    uint32_t r;
    asm("ex2.approx.f16x2 %0, %1;" : "=r"(r) : "r"(x));
    return r;
}
__device__ __forceinline__ uint32_t hadd2u(uint32_t a, uint32_t b) {
    __half2 r = __hadd2(*(__half2*)&a, *(__half2*)&b);
    return *(uint32_t*)&r;
}
__device__ __forceinline__ uint32_t pack2(float lo, float hi) {
    __half2 h = __floats2half2_rn(lo, hi);
    return *(uint32_t*)&h;
}

// ---------------------------------------------------------------------------
// Fused prep: X->fp16, Wqkv->fp16, Wproj->fp16, rp nibble-pack (permuted).
// ---------------------------------------------------------------------------
#define PREP_X  262144
#define PREP_WQ (PREP_X + 24576)
#define PREP_WP (PREP_WQ + 8192)
#define PREP_RP (PREP_WP + 262144)
#define PREP_BLOCKS ((PREP_RP + 255) / 256)

__global__ void __launch_bounds__(256) prep_kernel(
    const float4* __restrict__ X, const float4* __restrict__ Wq,
    const float4* __restrict__ Wp, const int4* __restrict__ rp)
{
    int idx = blockIdx.x * 256 + threadIdx.x;
    if (idx < PREP_WP) {
        const float4* src;
        uint4* dst;
        int i;
        if (idx < PREP_X)       { src = X;  dst = (uint4*)g_ah; i = idx; }
        else if (idx < PREP_WQ) { src = Wq; dst = (uint4*)g_wq; i = idx - PREP_X; }
        else                    { src = Wp; dst = (uint4*)g_wp; i = idx - PREP_WQ; }
        float4 a = src[i * 2], b = src[i * 2 + 1];
        __half2 h0 = __floats2half2_rn(a.x, a.y);
        __half2 h1 = __floats2half2_rn(a.z, a.w);
        __half2 h2 = __floats2half2_rn(b.x, b.y);
        __half2 h3 = __floats2half2_rn(b.z, b.w);
        dst[i] = make_uint4(*(uint32_t*)&h0, *(uint32_t*)&h1,
                            *(uint32_t*)&h2, *(uint32_t*)&h3);
    } else if (idx < PREP_RP) {
        int gI = idx - PREP_WP;
        int r[32];
        #pragma unroll
        for (int i = 0; i < 8; i++) {
            int4 v = rp[gI * 8 + i];
            r[i*4+0] = v.x; r[i*4+1] = v.y; r[i*4+2] = v.z; r[i*4+3] = v.w;
        }
        uint32_t w[4];
        #pragma unroll
        for (int t = 0; t < 4; t++) {
            uint32_t acc = 0;
            #pragma unroll
            for (int nt = 0; nt < 4; nt++) {
                uint32_t pair = (uint32_t)r[8*nt + 2*t] | ((uint32_t)r[8*nt + 2*t + 1] << 4);
                acc |= pair << (8 * nt);
            }
            w[t] = acc;
        }
        ((uint4*)g_rpn)[gI] = make_uint4(w[0], w[1], w[2], w[3]);
    }
}

// ---------------------------------------------------------------------------
// fp16 tensor-core GEMM: C[M,N] = A[M,256] @ W[256,N]
// block tile 64x128, K-chunks of 64, cp.async double buffer. 8 warps (2x4).
// ---------------------------------------------------------------------------
#define A_ROWB 144
#define B_ROWB 272
#define A_TILEB (64 * A_ROWB)            // 9216
#define B_TILEB (64 * B_ROWB)            // 17408
#define G_BUFB  (A_TILEB + B_TILEB)      // 26624
#define GEMM_SMEM (2 * G_BUFB)           // 53248

template<bool PROJ>
__global__ void __launch_bounds__(256) gemm_f16_kernel(
    const uint4* __restrict__ A4, const __half* __restrict__ Bh, int ldb,
    float* __restrict__ outp, const float* __restrict__ bias)
{
    extern __shared__ char smem[];
    const int tid  = threadIdx.x;
    const int warp = tid >> 5, lane = tid & 31;
    const int g = lane >> 2, t = lane & 3;
    const int m0 = blockIdx.y * 64, n0 = blockIdx.x * 128;
    const int wm = warp >> 2, wn = warp & 3;
    const uint32_t sb = smem_u32(smem);
    const int arow = lane & 15, chi = lane >> 4;

    float acc[2][4][4];
    #pragma unroll
    for (int mt = 0; mt < 2; mt++)
        #pragma unroll
        for (int nt = 0; nt < 4; nt++)
            #pragma unroll
            for (int r = 0; r < 4; r++) acc[mt][nt][r] = 0.f;

    auto load_chunk = [&](int c, int buf) {
        uint32_t base = sb + buf * G_BUFB;
        #pragma unroll
        for (int i = 0; i < 2; i++) {
            int idx = i * 256 + tid;
            int row = idx >> 3, cc = idx & 7;
            cp16(base + row * A_ROWB + cc * 16,
                 &A4[(long)(m0 + row) * 32 + c * 8 + cc]);
        }
        #pragma unroll
        for (int i = 0; i < 4; i++) {
            int idx = i * 256 + tid;
            int row = idx >> 4, cc = idx & 15;
            cp16(base + A_TILEB + row * B_ROWB + cc * 16,
                 Bh + (long)(c * 64 + row) * ldb + n0 + cc * 8);
        }
        cp_commit();
    };

    load_chunk(0, 0);

    for (int c = 0; c < 4; c++) {
        cp_wait0();
        __syncthreads();
        if (c < 3) load_chunk(c + 1, (c + 1) & 1);
        const uint32_t base = sb + (c & 1) * G_BUFB;
        const uint32_t bbase = base + A_TILEB;

        #pragma unroll
        for (int ks2 = 0; ks2 < 2; ks2++) {
            uint32_t bt[4][4];
            #pragma unroll
            for (int oct = 0; oct < 4; oct++)
                ldsm4t(bt[oct], bbase + (uint32_t)((ks2 * 32 + lane) * B_ROWB
                                                   + wn * 64 + oct * 16));
            #pragma unroll
            for (int r = 0; r < 2; r++) {
                uint32_t af[2][4];
                int s = ks2 * 2 + r;
                #pragma unroll
                for (int mt = 0; mt < 2; mt++)
                    ldsm4(af[mt], base + (uint32_t)((wm * 32 + mt * 16 + arow) * A_ROWB
                                                    + (2 * s + chi) * 16));
                #pragma unroll
                for (int mt = 0; mt < 2; mt++)
                    #pragma unroll
                    for (int nt = 0; nt < 4; nt++) {
                        uint32_t bb[2] = { bt[nt][2 * r], bt[nt][2 * r + 1] };
                        mma_f16(acc[mt][nt], af[mt], bb);
                    }
            }
        }
        __syncthreads();
    }

    if (PROJ) {
        #pragma unroll
        for (int mt = 0; mt < 2; mt++) {
            int m = m0 + wm * 32 + mt * 16 + g;
            #pragma unroll
            for (int nt = 0; nt < 4; nt++) {
                int col = n0 + wn * 32 + nt * 8 + 2 * t;
                float b0 = bias[col], b1 = bias[col + 1];
                *(float2*)&outp[(long)m * 256 + col] =
                    make_float2(acc[mt][nt][0] + b0, acc[mt][nt][1] + b1);
                *(float2*)&outp[(long)(m + 8) * 256 + col] =
                    make_float2(acc[mt][nt][2] + b0, acc[mt][nt][3] + b1);
            }
        }
    } else {
        const float scale = 0.25503483f;   // 32^-0.5 * log2(e)
        #pragma unroll
        for (int mt = 0; mt < 2; mt++) {
            int m = m0 + wm * 32 + mt * 16 + g;
            int bb = m >> 10, nn = m & 1023;
            #pragma unroll
            for (int nt = 0; nt < 4; nt++) {
                int col = n0 + wn * 32 + nt * 8 + 2 * t;
                int sel = col >> 8, hh = (col >> 5) & 7, dd = col & 31;
                float c0 = acc[mt][nt][0], c1 = acc[mt][nt][1];
                float c2 = acc[mt][nt][2], c3 = acc[mt][nt][3];
                if (sel == 0) { c0 *= scale; c1 *= scale; c2 *= scale; c3 *= scale; }
                __half* dst = (sel == 0) ? g_qh : (sel == 1) ? g_kh : g_vh;
                long base = (((long)bb * HH + hh) * NN + nn) * HD + dd;
                *(__half2*)&dst[base]           = __floats2half2_rn(c0, c1);
                *(__half2*)&dst[base + 8 * HD]  = __floats2half2_rn(c2, c3);
            }
        }
    }
}

// ---------------------------------------------------------------------------
// Fused flash attention v7: block = (batch, head, 128 q-rows), grid 512
// (single wave at occ 4). 4 warps x 32 rows (2 m-tiles per warp); K/V frags
// loaded once per warp-tile and reused by both m-tiles. Fixed-shift ex2
// softmax, ones-column row sums.
// ---------------------------------------------------------------------------
#define AKROWB 80
#define AKTILE (32 * AKROWB)             // 2560
#define ARPB   2048                      // 128 rows x 16 B rpn slice
#define ASTAGE (2 * AKTILE + ARPB)       // 7168
#define ATT_SMEM (2 * ASTAGE + 640)      // 14976
#define SOFT_SHIFT 4.0f

__global__ void __launch_bounds__(128, 4) attn_mma_kernel(
    const int* __restrict__ rel_len, const float* __restrict__ bias_table)
{
    extern __shared__ char smc[];
    const uint32_t sb = smem_u32(smc);

    const int tid  = threadIdx.x;
    const int w    = tid >> 5;               // warp 0..3 -> 32-row span
    const int lane = tid & 31;
    const int g    = lane >> 2;
    const int t    = lane & 3;
    const int b     = blockIdx.x >> 6;
    const int h     = (blockIdx.x >> 3) & 7;
    const int chunk = blockIdx.x & 7;
    const int row0  = chunk * 128;

    uint32_t* tblp = (uint32_t*)(smc + 2 * ASTAGE);

    // per-head masked bias pair table (log2 domain)
    {
        const int mask_len = (int)(__int2float_rn(rel_len[b]) * 0.5f);
        for (int i = tid; i < 160; i += 128) {
            int lo = i & 15, hi = i >> 4;
            float vlo = (lo < TABLE)
                ? bias_table[lo * HH + h] * 1.4426950408889634f
                  + ((lo > mask_len) ? -144.2695040888963f : 0.f) : 0.f;
            float vhi = bias_table[hi * HH + h] * 1.4426950408889634f
                  + ((hi > mask_len) ? -144.2695040888963f : 0.f);
            tblp[i] = pack2(vlo, vhi);
        }
    }
    // V pad columns (d=32..39) = fp16 ones, both stages
    if (tid < 64) {
        const uint4 ones = make_uint4(0x3C003C00u, 0x3C003C00u, 0x3C003C00u, 0x3C003C00u);
        int stg = tid >> 5, row = tid & 31;
        *(uint4*)(smc + stg * ASTAGE + AKTILE + row * AKROWB + 64) = ones;
    }

    // Q fragments: warp w's 32 rows (2 m-tiles), scale*log2e pre-folded
    uint32_t qa[2][2][4];
    {
        const uint32_t* qw = (const uint32_t*)g_qh;
        long rbase = ((long)(b * HH) + h) * NN + row0 + w * 32;
        #pragma unroll
        for (int mt = 0; mt < 2; mt++) {
            long rA = (rbase + mt * 16 + g) * 16, rB = rA + 128;
            #pragma unroll
            for (int ks = 0; ks < 2; ks++) {
                int wd = ks * 8 + t;
                qa[mt][ks][0] = qw[rA + wd];
                qa[mt][ks][1] = qw[rB + wd];
                qa[mt][ks][2] = qw[rA + wd + 4];
                qa[mt][ks][3] = qw[rB + wd + 4];
            }
        }
    }

    float o[2][5][4];                        // nt=4 is ones column (row sums)
    #pragma unroll
    for (int mt = 0; mt < 2; mt++)
        #pragma unroll
        for (int nt = 0; nt < 5; nt++)
            #pragma unroll
            for (int r = 0; r < 4; r++) o[mt][nt][r] = 0.f;

    const __half*  gk   = g_kh;
    const __half*  gv   = g_vh;
    const uint8_t* grpn = g_rpn;
    const long kvhead = ((long)(b * HH) + h) * NN * HD;
    const long rpnrow = ((long)b * NN + row0) * (NN / 2);

    // cooperative prefetch of tile j into stage stg (128 threads)
    auto prefetch = [&](int j, int stg) {
        uint32_t base = sb + stg * ASTAGE;
        long src = kvhead + (long)(j * 32) * HD;
        int row = tid >> 2, ch = tid & 3;
        uint32_t d = base + row * AKROWB + ch * 16;
        cp16(d, gk + src + row * HD + ch * 8);
        cp16(d + AKTILE, gv + src + row * HD + ch * 8);
        // rpn: 128 rows x 16 B for this key tile
        cp16(base + 2 * AKTILE + tid * 16, grpn + rpnrow + (long)tid * 512 + j * 16);
        cp_commit();
    };

    prefetch(0, 0);

    const int ln8 = lane & 7, l8 = lane >> 3;

    for (int j = 0; j < 32; j++) {
        const int stg = j & 1;
        cp_wait0();
        __syncthreads();                     // stage stg ready; stage stg^1 free
        if (j < 31) prefetch(j + 1, stg ^ 1);

        const uint32_t kbase = sb + stg * ASTAGE;
        const uint32_t vbase = kbase + AKTILE;
        const char*    rpn_s = smc + stg * ASTAGE + 2 * AKTILE;

        // ---- K frags once, S for both m-tiles (acc preloaded with -SHIFT) ----
        float c[2][4][4];
        #pragma unroll
        for (int mt = 0; mt < 2; mt++)
            #pragma unroll
            for (int nt = 0; nt < 4; nt++)
                #pragma unroll
                for (int r = 0; r < 4; r++) c[mt][nt][r] = -SOFT_SHIFT;
        {
            uint32_t kb[4][4];
            uint32_t ka = kbase + (uint32_t)(ln8 * AKROWB + l8 * 16);
            #pragma unroll
            for (int nt = 0; nt < 4; nt++)
                ldsm4(kb[nt], ka + nt * (8 * AKROWB));
            #pragma unroll
            for (int nt = 0; nt < 4; nt++)
                #pragma unroll
                for (int ks = 0; ks < 2; ks++) {
                    uint32_t bf[2] = { kb[nt][2 * ks], kb[nt][2 * ks + 1] };
                    mma_f16(c[0][nt], qa[0][ks], bf);
                    mma_f16(c[1][nt], qa[1][ks], bf);
                }
        }

        // ---- V frags once (shared by both m-tiles) ----
        uint32_t vb[5][4];
        {
            uint32_t va = vbase + (uint32_t)(lane * AKROWB);
            #pragma unroll
            for (int nt = 0; nt < 5; nt++)
                ldsm4t(vb[nt], va + nt * 16);
        }

        // ---- bias + fixed-shift ex2 softmax -> P A-frags, then PV ----
        #pragma unroll
        for (int mt = 0; mt < 2; mt++) {
            int rAr = w * 32 + mt * 16 + g;
            uint32_t wA = *(const uint32_t*)(rpn_s + rAr * 16 + t * 4);
            uint32_t wB = *(const uint32_t*)(rpn_s + (rAr + 8) * 16 + t * 4);
            uint32_t hA[4], hB[4];
            #pragma unroll
            for (int nt = 0; nt < 4; nt++) {
                uint32_t iA = (wA >> (8 * nt)) & 0xFF;
                uint32_t iB = (wB >> (8 * nt)) & 0xFF;
                hA[nt] = ex2h2(hadd2u(pack2(c[mt][nt][0], c[mt][nt][1]), tblp[iA]));
                hB[nt] = ex2h2(hadd2u(pack2(c[mt][nt][2], c[mt][nt][3]), tblp[iB]));
            }
            uint32_t pa[2][4];
            #pragma unroll
            for (int ks = 0; ks < 2; ks++) {
                pa[ks][0] = hA[2 * ks];
                pa[ks][1] = hB[2 * ks];
                pa[ks][2] = hA[2 * ks + 1];
                pa[ks][3] = hB[2 * ks + 1];
            }
            #pragma unroll
            for (int ks = 0; ks < 2; ks++)
                #pragma unroll
                for (int nt = 0; nt < 5; nt++) {
                    uint32_t bf[2] = { vb[nt][2 * ks], vb[nt][2 * ks + 1] };
                    mma_f16(o[mt][nt], pa[ks], bf);
                }
        }
    }

    // ---- epilogue: normalize by ones-column sums, store fp16 to g_xh ----
    #pragma unroll
    for (int mt = 0; mt < 2; mt++) {
        float i0 = 1.f / o[mt][4][0];
        float i1 = 1.f / o[mt][4][2];
        int rA = row0 + w * 32 + mt * 16 + g;
        #pragma unroll
        for (int nt = 0; nt < 4; nt++) {
            int col = h * HD + nt * 8 + 2 * t;
            *(__half2*)&g_xh[((long)b * NN + rA) * CC + col] =
                __floats2half2_rn(o[mt][nt][0] * i0, o[mt][nt][1] * i0);
            *(__half2*)&g_xh[((long)b * NN + rA + 8) * CC + col] =
                __floats2half2_rn(o[mt][nt][2] * i1, o[mt][nt][3] * i1);
        }
    }
}

// ---------------------------------------------------------------------------
extern "C" void kernel_launch(void* const* d_in, const int* in_sizes, int n_in,
                              void* d_out, int out_size)
{
    const float* X       = (const float*)d_in[0];
    const int*   rp      = (const int*)  d_in[1];
    const int*   rel_len = (const int*)  d_in[2];
    const float* Wqkv    = (const float*)d_in[3];
    const float* Wproj   = (const float*)d_in[4];
    const float* bproj   = (const float*)d_in[5];
    const float* btab    = (const float*)d_in[6];
    float* out = (float*)d_out;

    __half* d_ah;  cudaGetSymbolAddress((void**)&d_ah, g_ah);
    __half* d_wq;  cudaGetSymbolAddress((void**)&d_wq, g_wq);
    __half* d_wp;  cudaGetSymbolAddress((void**)&d_wp, g_wp);
    __half* d_xh;  cudaGetSymbolAddress((void**)&d_xh, g_xh);

    // 1) fused prep: converts + rp nibble pack
    prep_kernel<<<PREP_BLOCKS, 256>>>((const float4*)X, (const float4*)Wqkv,
                                      (const float4*)Wproj, (const int4*)rp);

    // 2) qkv GEMM (64x128 tiles, 768 blocks)
    cudaFuncSetAttribute(gemm_f16_kernel<false>,
                         cudaFuncAttributeMaxDynamicSharedMemorySize, GEMM_SMEM);
    gemm_f16_kernel<false><<<dim3(6, 128), 256, GEMM_SMEM>>>(
        (const uint4*)d_ah, d_wq, 768, nullptr, nullptr);

    // 3) attention (512 blocks x 128 threads, single wave)
    attn_mma_kernel<<<BB * HH * 8, 128, ATT_SMEM>>>(rel_len, btab);

    // 4) proj GEMM (64x128 tiles, 256 blocks) + bias -> fp32 out
    cudaFuncSetAttribute(gemm_f16_kernel<true>,
                         cudaFuncAttributeMaxDynamicSharedMemorySize, GEMM_SMEM);
    gemm_f16_kernel<true><<<dim3(2, 128), 256, GEMM_SMEM>>>(
        (const uint4*)d_xh, d_wp, 256, out, bproj);
}